// round 2
// baseline (speedup 1.0000x reference)
#include <cuda_runtime.h>
#include <cstdint>
#include <math.h>

#define NB 2
#define NS 2048
#define NHID 2048
#define NHEADS 16
#define NKVH 4
#define DHEAD 128
#define NQKV 3072

// ------------------------- scratch (static device globals; no allocs) ------
static __device__ float g_qkv[(size_t)NB * NS * NQKV];           // 50.3 MB
static __device__ float g_q[(size_t)NB * NHEADS * NS * DHEAD];   // 33.5 MB
static __device__ float g_k[(size_t)NB * NKVH * NS * DHEAD];     // 8.4 MB
static __device__ float g_v[(size_t)NB * NKVH * NS * DHEAD];     // 8.4 MB
static __device__ float g_attn[(size_t)NB * NS * NHID];          // 33.5 MB

// ------------------------- generic SGEMM: C[M,N] = A[M,K] * B[N,K]^T -------
// BM=BN=128, BK=8, 256 threads, 8x8 microtile. M,N % 128 == 0, K % 8 == 0.
template <int CLAMP>
__global__ void __launch_bounds__(256) sgemm_nt(const float* __restrict__ A,
                                                const float* __restrict__ Bw,
                                                float* __restrict__ C,
                                                int M, int N, int K) {
    __shared__ float As[8][128];
    __shared__ float Bs[8][128];
    const int tid = threadIdx.x;
    const int tx = tid & 15;        // column group
    const int ty = tid >> 4;        // row group
    const int bx = blockIdx.x;      // N tile
    const int by = blockIdx.y;      // M tile

    const int lrow = tid >> 1;          // 0..127
    const int lc = (tid & 1) * 4;       // 0 or 4

    const float* Ap = A + (size_t)(by * 128 + lrow) * K + lc;
    const float* Bp = Bw + (size_t)(bx * 128 + lrow) * K + lc;

    float acc[8][8];
#pragma unroll
    for (int i = 0; i < 8; i++)
#pragma unroll
        for (int j = 0; j < 8; j++) acc[i][j] = 0.0f;

    for (int k0 = 0; k0 < K; k0 += 8) {
        float4 a4 = *(const float4*)(Ap + k0);
        float4 b4 = *(const float4*)(Bp + k0);
        __syncthreads();
        As[lc + 0][lrow] = a4.x; As[lc + 1][lrow] = a4.y;
        As[lc + 2][lrow] = a4.z; As[lc + 3][lrow] = a4.w;
        Bs[lc + 0][lrow] = b4.x; Bs[lc + 1][lrow] = b4.y;
        Bs[lc + 2][lrow] = b4.z; Bs[lc + 3][lrow] = b4.w;
        __syncthreads();
#pragma unroll
        for (int kk = 0; kk < 8; kk++) {
            float ra[8], rb[8];
#pragma unroll
            for (int i = 0; i < 8; i++) ra[i] = As[kk][ty + 16 * i];
#pragma unroll
            for (int j = 0; j < 8; j++) rb[j] = Bs[kk][tx + 16 * j];
#pragma unroll
            for (int i = 0; i < 8; i++)
#pragma unroll
                for (int j = 0; j < 8; j++) acc[i][j] += ra[i] * rb[j];
        }
    }

#pragma unroll
    for (int i = 0; i < 8; i++) {
        float* crow = C + (size_t)(by * 128 + ty + 16 * i) * N + bx * 128;
#pragma unroll
        for (int j = 0; j < 8; j++) {
            float v = acc[i][j];
            if (CLAMP) v = fminf(8.0f, fmaxf(-8.0f, v));
            crow[tx + 16 * j] = v;
        }
    }
}

// ------------------------- RoPE + scatter ----------------------------------
// one block per (b,s), 128 threads = head dim. Double-precision angles so
// trig matches the fp32 reference to well under tolerance.
// position_ids may be int32 (JAX x64 disabled) or int64 — sniff the layout:
// for int64 values < 2^31 the odd 32-bit words are all zero.
__global__ void __launch_bounds__(128) rope_scatter(const void* __restrict__ pos_ids) {
    const int bs = blockIdx.x;          // 0 .. NB*NS-1
    const int b = bs / NS;
    const int s = bs % NS;
    const int d = threadIdx.x;          // 0..127
    const int dm = d & 63;

    const int* p32 = (const int*)pos_ids;
    const bool is64 = (p32[1] == 0) && (p32[3] == 0) && (p32[2 * NS + 1] == 0);
    const long long pv = is64 ? ((const long long*)pos_ids)[bs] : (long long)p32[bs];

    const double p = (double)pv;
    const double invf = pow(500000.0, -(double)dm / 64.0);
    double sd, cd;
    sincos(p * invf, &sd, &cd);
    const float c = (float)cd;
    const float sn = (float)sd;
    const float sign = (d < 64) ? -1.0f : 1.0f;
    const float qscale = 0.08838834764831845f;  // 1/sqrt(128)

    const float* row = g_qkv + (size_t)bs * NQKV;

#pragma unroll
    for (int h = 0; h < NHEADS; h++) {
        float v = row[h * DHEAD + d];
        float pr = row[h * DHEAD + (d ^ 64)];
        g_q[(((size_t)b * NHEADS + h) * NS + s) * DHEAD + d] =
            (v * c + sign * pr * sn) * qscale;
    }
#pragma unroll
    for (int h = 0; h < NKVH; h++) {
        float v = row[NHID + h * DHEAD + d];
        float pr = row[NHID + h * DHEAD + (d ^ 64)];
        g_k[(((size_t)b * NKVH + h) * NS + s) * DHEAD + d] = v * c + sign * pr * sn;
        g_v[(((size_t)b * NKVH + h) * NS + s) * DHEAD + d] =
            row[NHID + NKVH * DHEAD + h * DHEAD + d];
    }
}

// ------------------------- flash attention (fp32, causal, GQA) -------------
// BM=BN=64, 256 threads. Thread (ty,tx): score rows {4ty+i}, score cols
// {tx+16j}, output cols {tx+16jj}. Q pre-scaled by 1/sqrt(HD).
__global__ void __launch_bounds__(256) flash_attn() {
    extern __shared__ float sm[];
    float* Qs = sm;                        // [64][129]
    float* Ks = Qs + 64 * 129;             // [64][129]
    float* Vs = Ks + 64 * 129;             // [64][128]
    float* Ps = Vs + 64 * 128;             // [64][65]

    const int tid = threadIdx.x;
    const int tx = tid & 15;
    const int ty = tid >> 4;
    const int qb = gridDim.x - 1 - blockIdx.x;  // heaviest tiles first
    const int h = blockIdx.y;
    const int b = blockIdx.z;
    const int hk = h >> 2;                  // GQA: 4 q heads per kv head
    const int q0 = qb * 64;

    const float* Qg = g_q + (((size_t)b * NHEADS + h) * NS + q0) * DHEAD;
    const float* Kg = g_k + (((size_t)b * NKVH + hk) * NS) * DHEAD;
    const float* Vg = g_v + (((size_t)b * NKVH + hk) * NS) * DHEAD;

    for (int i = tid; i < 64 * 32; i += 256) {
        int r = i >> 5, cc = (i & 31) * 4;
        float4 q4 = *(const float4*)(Qg + r * DHEAD + cc);
        float* dst = Qs + r * 129 + cc;
        dst[0] = q4.x; dst[1] = q4.y; dst[2] = q4.z; dst[3] = q4.w;
    }

    float m_i[4], l_i[4], acc[4][8];
#pragma unroll
    for (int i = 0; i < 4; i++) {
        m_i[i] = -1e30f;
        l_i[i] = 0.0f;
#pragma unroll
        for (int j = 0; j < 8; j++) acc[i][j] = 0.0f;
    }

    const int ntiles = qb + 1;
    for (int t = 0; t < ntiles; t++) {
        const float* Kt = Kg + (size_t)t * 64 * DHEAD;
        const float* Vt = Vg + (size_t)t * 64 * DHEAD;
        __syncthreads();
        for (int i = tid; i < 64 * 32; i += 256) {
            int r = i >> 5, cc = (i & 31) * 4;
            float4 k4 = *(const float4*)(Kt + r * DHEAD + cc);
            float* kd = Ks + r * 129 + cc;
            kd[0] = k4.x; kd[1] = k4.y; kd[2] = k4.z; kd[3] = k4.w;
            float4 v4 = *(const float4*)(Vt + r * DHEAD + cc);
            *(float4*)(Vs + r * DHEAD + cc) = v4;
        }
        __syncthreads();

        // S = Q * K^T  (16 scores per thread)
        float sc[4][4];
#pragma unroll
        for (int i = 0; i < 4; i++)
#pragma unroll
            for (int j = 0; j < 4; j++) sc[i][j] = 0.0f;

#pragma unroll 4
        for (int k = 0; k < DHEAD; k++) {
            float rq[4], rk[4];
#pragma unroll
            for (int i = 0; i < 4; i++) rq[i] = Qs[(4 * ty + i) * 129 + k];
#pragma unroll
            for (int j = 0; j < 4; j++) rk[j] = Ks[(tx + 16 * j) * 129 + k];
#pragma unroll
            for (int i = 0; i < 4; i++)
#pragma unroll
                for (int j = 0; j < 4; j++) sc[i][j] += rq[i] * rk[j];
        }

        if (t == qb) {  // diagonal tile: causal mask
#pragma unroll
            for (int i = 0; i < 4; i++)
#pragma unroll
                for (int j = 0; j < 4; j++)
                    if (tx + 16 * j > 4 * ty + i) sc[i][j] = -1e30f;
        }

        // online softmax per row
#pragma unroll
        for (int i = 0; i < 4; i++) {
            float mx = fmaxf(fmaxf(sc[i][0], sc[i][1]), fmaxf(sc[i][2], sc[i][3]));
            mx = fmaxf(mx, __shfl_xor_sync(0xffffffffu, mx, 1));
            mx = fmaxf(mx, __shfl_xor_sync(0xffffffffu, mx, 2));
            mx = fmaxf(mx, __shfl_xor_sync(0xffffffffu, mx, 4));
            mx = fmaxf(mx, __shfl_xor_sync(0xffffffffu, mx, 8));
            float mnew = fmaxf(m_i[i], mx);
            float scale = __expf(m_i[i] - mnew);
            float rs = 0.0f;
#pragma unroll
            for (int j = 0; j < 4; j++) {
                float pexp = __expf(sc[i][j] - mnew);
                sc[i][j] = pexp;
                rs += pexp;
            }
            rs += __shfl_xor_sync(0xffffffffu, rs, 1);
            rs += __shfl_xor_sync(0xffffffffu, rs, 2);
            rs += __shfl_xor_sync(0xffffffffu, rs, 4);
            rs += __shfl_xor_sync(0xffffffffu, rs, 8);
            l_i[i] = l_i[i] * scale + rs;
            m_i[i] = mnew;
#pragma unroll
            for (int jj = 0; jj < 8; jj++) acc[i][jj] *= scale;
#pragma unroll
            for (int j = 0; j < 4; j++)
                Ps[(4 * ty + i) * 65 + tx + 16 * j] = sc[i][j];
        }
        __syncthreads();

        // O += P * V
#pragma unroll 4
        for (int j = 0; j < 64; j++) {
            float pv[4];
#pragma unroll
            for (int i = 0; i < 4; i++) pv[i] = Ps[(4 * ty + i) * 65 + j];
#pragma unroll
            for (int jj = 0; jj < 8; jj++) {
                float vv = Vs[j * DHEAD + tx + 16 * jj];
#pragma unroll
                for (int i = 0; i < 4; i++) acc[i][jj] += pv[i] * vv;
            }
        }
    }

#pragma unroll
    for (int i = 0; i < 4; i++) {
        float inv = 1.0f / l_i[i];
        int q = q0 + 4 * ty + i;
        float* outp = g_attn + ((size_t)b * NS + q) * NHID + h * DHEAD;
#pragma unroll
        for (int jj = 0; jj < 8; jj++) outp[tx + 16 * jj] = acc[i][jj] * inv;
    }
}

// ------------------------- launch ------------------------------------------
extern "C" void kernel_launch(void* const* d_in, const int* in_sizes, int n_in,
                              void* d_out, int out_size) {
    const float* hidden = (const float*)d_in[0];
    const void* pos = d_in[1];
    const float* Wqkv = (const float*)d_in[2];
    const float* Wout = (const float*)d_in[3];
    float* out = (float*)d_out;

    void *p_qkv, *p_attn;
    cudaGetSymbolAddress(&p_qkv, g_qkv);
    cudaGetSymbolAddress(&p_attn, g_attn);

    // 1) QKV projection + clamp
    {
        dim3 grid(NQKV / 128, (NB * NS) / 128);
        sgemm_nt<1><<<grid, 256>>>(hidden, Wqkv, (float*)p_qkv,
                                   NB * NS, NQKV, NHID);
    }
    // 2) RoPE + scatter to [b, h, s, d] (Q scaled by 1/sqrt(HD))
    rope_scatter<<<NB * NS, 128>>>(pos);

    // 3) causal flash attention
    {
        const int smem = (64 * 129 + 64 * 129 + 64 * 128 + 64 * 65) * 4;  // 115456
        cudaFuncSetAttribute(flash_attn, cudaFuncAttributeMaxDynamicSharedMemorySize, smem);
        dim3 grid(NS / 64, NHEADS, NB);
        flash_attn<<<grid, 256, smem>>>();
    }
    // 4) output projection
    {
        dim3 grid(NHID / 128, (NB * NS) / 128);
        sgemm_nt<0><<<grid, 256>>>((const float*)p_attn, Wout, out,
                                   NB * NS, NHID, NHID);
    }
}

// round 4
// speedup vs baseline: 1.6780x; 1.6780x over previous
#include <cuda_runtime.h>
#include <cuda_bf16.h>
#include <cstdint>
#include <math.h>

#define NB 2
#define NS 2048
#define NHID 2048
#define NHEADS 16
#define NKVH 4
#define DHEAD 128
#define NQKV 3072

// ------------------------- scratch (static device globals; no allocs) ------
static __device__ float g_qkv[(size_t)NB * NS * NQKV];
static __device__ float g_q[(size_t)NB * NHEADS * NS * DHEAD];
static __device__ float g_k[(size_t)NB * NKVH * NS * DHEAD];
static __device__ float g_v[(size_t)NB * NKVH * NS * DHEAD];
static __device__ float g_attn[(size_t)NB * NS * NHID];

// bf16 hi/lo split operands
static __device__ __nv_bfloat16 g_hid_hi[(size_t)NB * NS * NHID];
static __device__ __nv_bfloat16 g_hid_lo[(size_t)NB * NS * NHID];
static __device__ __nv_bfloat16 g_w1_hi[(size_t)NQKV * NHID];
static __device__ __nv_bfloat16 g_w1_lo[(size_t)NQKV * NHID];
static __device__ __nv_bfloat16 g_w2_hi[(size_t)NHID * NHID];
static __device__ __nv_bfloat16 g_w2_lo[(size_t)NHID * NHID];
static __device__ __nv_bfloat16 g_at_hi[(size_t)NB * NS * NHID];
static __device__ __nv_bfloat16 g_at_lo[(size_t)NB * NS * NHID];

// ------------------------- PTX helpers (baseline ISA only) -----------------
__device__ __forceinline__ uint32_t smem_u32(const void* p) {
    uint32_t a;
    asm("{ .reg .u64 t; cvta.to.shared.u64 t, %1; cvt.u32.u64 %0, t; }"
        : "=r"(a) : "l"(p));
    return a;
}

__device__ __forceinline__ void cp16(uint32_t dst, const void* src) {
    asm volatile("cp.async.cg.shared.global [%0], [%1], 16;"
                 :: "r"(dst), "l"(src));
}
#define CP_COMMIT() asm volatile("cp.async.commit_group;" ::: "memory")
#define CP_WAIT0() asm volatile("cp.async.wait_group 0;" ::: "memory")
#define CP_WAIT1() asm volatile("cp.async.wait_group 1;" ::: "memory")

__device__ __forceinline__ void ldsm4(uint32_t* r, uint32_t addr) {
    asm volatile("ldmatrix.sync.aligned.m8n8.x4.shared.b16 {%0,%1,%2,%3}, [%4];"
                 : "=r"(r[0]), "=r"(r[1]), "=r"(r[2]), "=r"(r[3]) : "r"(addr));
}

__device__ __forceinline__ void mma16816(float* c, const uint32_t* a, const uint32_t* b) {
    asm volatile(
        "mma.sync.aligned.m16n8k16.row.col.f32.bf16.bf16.f32 "
        "{%0,%1,%2,%3}, {%4,%5,%6,%7}, {%8,%9}, {%0,%1,%2,%3};"
        : "+f"(c[0]), "+f"(c[1]), "+f"(c[2]), "+f"(c[3])
        : "r"(a[0]), "r"(a[1]), "r"(a[2]), "r"(a[3]), "r"(b[0]), "r"(b[1]));
}

// ------------------------- split fp32 -> bf16 hi/lo ------------------------
__global__ void __launch_bounds__(256) split_bf16(const float* __restrict__ x,
                                                  __nv_bfloat16* __restrict__ hi,
                                                  __nv_bfloat16* __restrict__ lo,
                                                  int n4) {
    int i = blockIdx.x * 256 + threadIdx.x;
    if (i >= n4) return;
    float4 v = ((const float4*)x)[i];
    __nv_bfloat16 h0 = __float2bfloat16(v.x), h1 = __float2bfloat16(v.y);
    __nv_bfloat16 h2 = __float2bfloat16(v.z), h3 = __float2bfloat16(v.w);
    __nv_bfloat162 hh0 = {h0, h1}, hh1 = {h2, h3};
    ((__nv_bfloat162*)hi)[2 * i] = hh0;
    ((__nv_bfloat162*)hi)[2 * i + 1] = hh1;
    __nv_bfloat162 ll0 = {__float2bfloat16(v.x - __bfloat162float(h0)),
                          __float2bfloat16(v.y - __bfloat162float(h1))};
    __nv_bfloat162 ll1 = {__float2bfloat16(v.z - __bfloat162float(h2)),
                          __float2bfloat16(v.w - __bfloat162float(h3))};
    ((__nv_bfloat162*)lo)[2 * i] = ll0;
    ((__nv_bfloat162*)lo)[2 * i + 1] = ll1;
}

// ------------------------- HMMA GEMM: C[M,N] = A[M,K] * B[N,K]^T -----------
// bf16 hi/lo 3-pass. 128x128 tile, BK=32, 256 threads, double-buffered
// cp.async. Smem rows padded to 80B -> conflict-free ldmatrix (5 odd).
#define ROWB 80
#define OPSZ (128 * ROWB)          // 10240 per operand tile
#define STAGESZ (4 * OPSZ)         // Ahi, Alo, Bhi, Blo
#define GSMEM (2 * STAGESZ)        // 81920

template <int CLAMP>
__global__ void __launch_bounds__(256) gemm_hmma(const __nv_bfloat16* __restrict__ Ahi,
                                                 const __nv_bfloat16* __restrict__ Alo,
                                                 const __nv_bfloat16* __restrict__ Bhi,
                                                 const __nv_bfloat16* __restrict__ Blo,
                                                 float* __restrict__ C,
                                                 int M, int N, int K) {
    extern __shared__ char smem[];
    const uint32_t sb = smem_u32(smem);
    const int tid = threadIdx.x;
    const int lane = tid & 31;
    const int wid = tid >> 5;
    const int wm = (wid & 1) * 64;   // warp m offset within tile
    const int wn = (wid >> 1) * 32;  // warp n offset
    const int bx = blockIdx.x;
    const int by = blockIdx.y;

    // load task: thread covers tasks tid and tid+256 per operand
    const int r0 = tid >> 2, c0 = (tid & 3);        // task tid
    const int r1 = (tid + 256) >> 2, c1 = tid & 3;  // task tid+256

    const __nv_bfloat16* gA[2] = {Ahi, Alo};
    const __nv_bfloat16* gB[2] = {Bhi, Blo};

    auto load_stage = [&](int stage, int kt) {
        const uint32_t s = sb + stage * STAGESZ;
        const int kc = kt * 32;
#pragma unroll
        for (int hl = 0; hl < 2; hl++) {
            const __nv_bfloat16* A = gA[hl] + (size_t)(by * 128) * K + kc;
            const __nv_bfloat16* B = gB[hl] + (size_t)(bx * 128) * K + kc;
            const uint32_t sA = s + hl * OPSZ;
            const uint32_t sB = s + (2 + hl) * OPSZ;
            cp16(sA + r0 * ROWB + c0 * 16, A + (size_t)r0 * K + c0 * 8);
            cp16(sA + r1 * ROWB + c1 * 16, A + (size_t)r1 * K + c1 * 8);
            cp16(sB + r0 * ROWB + c0 * 16, B + (size_t)r0 * K + c0 * 8);
            cp16(sB + r1 * ROWB + c1 * 16, B + (size_t)r1 * K + c1 * 8);
        }
    };

    float acc[4][4][4];
#pragma unroll
    for (int i = 0; i < 4; i++)
#pragma unroll
        for (int j = 0; j < 4; j++)
#pragma unroll
            for (int e = 0; e < 4; e++) acc[i][j][e] = 0.0f;

    const int KT = K >> 5;
    load_stage(0, 0);
    CP_COMMIT();

    // ldmatrix lane addressing within a 16-row x 16-col (2-chunk) block
    const int lrow = (lane & 7) + ((lane >> 3) & 1) * 8;
    const int lchunk = lane >> 4;  // 0..1

    for (int kt = 0; kt < KT; kt++) {
        if (kt + 1 < KT) {
            load_stage((kt + 1) & 1, kt + 1);
            CP_COMMIT();
            CP_WAIT1();
        } else {
            CP_WAIT0();
        }
        __syncthreads();

        const uint32_t s = sb + (kt & 1) * STAGESZ;
#pragma unroll
        for (int ks = 0; ks < 2; ks++) {  // two k16 steps per BK=32
            const int cb = 2 * ks;
            uint32_t ah[4][4], al[4][4], bh[4][2], bl[4][2];
#pragma unroll
            for (int mf = 0; mf < 4; mf++) {
                const uint32_t ra = (wm + mf * 16 + lrow) * ROWB + (cb + lchunk) * 16;
                ldsm4(ah[mf], s + ra);
                ldsm4(al[mf], s + OPSZ + ra);
            }
#pragma unroll
            for (int nf2 = 0; nf2 < 2; nf2++) {
                const uint32_t rb = (wn + nf2 * 16 + lrow) * ROWB + (cb + lchunk) * 16;
                uint32_t th[4], tl[4];
                ldsm4(th, s + 2 * OPSZ + rb);
                ldsm4(tl, s + 3 * OPSZ + rb);
                bh[nf2 * 2][0] = th[0]; bh[nf2 * 2 + 1][0] = th[1];
                bh[nf2 * 2][1] = th[2]; bh[nf2 * 2 + 1][1] = th[3];
                bl[nf2 * 2][0] = tl[0]; bl[nf2 * 2 + 1][0] = tl[1];
                bl[nf2 * 2][1] = tl[2]; bl[nf2 * 2 + 1][1] = tl[3];
            }
#pragma unroll
            for (int mf = 0; mf < 4; mf++)
#pragma unroll
                for (int nf = 0; nf < 4; nf++) {
                    mma16816(acc[mf][nf], ah[mf], bh[nf]);
                    mma16816(acc[mf][nf], ah[mf], bl[nf]);
                    mma16816(acc[mf][nf], al[mf], bh[nf]);
                }
        }
        __syncthreads();
    }

    // epilogue: write accumulators
    const int erow = lane >> 2;
    const int ecol = (lane & 3) * 2;
#pragma unroll
    for (int mf = 0; mf < 4; mf++) {
#pragma unroll
        for (int nf = 0; nf < 4; nf++) {
            float* c = acc[mf][nf];
            if (CLAMP) {
#pragma unroll
                for (int e = 0; e < 4; e++)
                    c[e] = fminf(8.0f, fmaxf(-8.0f, c[e]));
            }
            const int row = by * 128 + wm + mf * 16 + erow;
            const int col = bx * 128 + wn + nf * 8 + ecol;
            float2 v0 = {c[0], c[1]};
            float2 v1 = {c[2], c[3]};
            *(float2*)(C + (size_t)row * N + col) = v0;
            *(float2*)(C + (size_t)(row + 8) * N + col) = v1;
        }
    }
}

// ------------------------- RoPE + scatter ----------------------------------
__global__ void __launch_bounds__(128) rope_scatter(const void* __restrict__ pos_ids) {
    const int bs = blockIdx.x;
    const int b = bs / NS;
    const int s = bs % NS;
    const int d = threadIdx.x;
    const int dm = d & 63;

    const int* p32 = (const int*)pos_ids;
    const bool is64 = (p32[1] == 0) && (p32[3] == 0) && (p32[2 * NS + 1] == 0);
    const long long pv = is64 ? ((const long long*)pos_ids)[bs] : (long long)p32[bs];

    const double p = (double)pv;
    const double invf = pow(500000.0, -(double)dm / 64.0);
    double sd, cd;
    sincos(p * invf, &sd, &cd);
    const float c = (float)cd;
    const float sn = (float)sd;
    const float sign = (d < 64) ? -1.0f : 1.0f;
    const float qscale = 0.08838834764831845f;

    const float* row = g_qkv + (size_t)bs * NQKV;

#pragma unroll
    for (int h = 0; h < NHEADS; h++) {
        float v = row[h * DHEAD + d];
        float pr = row[h * DHEAD + (d ^ 64)];
        g_q[(((size_t)b * NHEADS + h) * NS + s) * DHEAD + d] =
            (v * c + sign * pr * sn) * qscale;
    }
#pragma unroll
    for (int h = 0; h < NKVH; h++) {
        float v = row[NHID + h * DHEAD + d];
        float pr = row[NHID + h * DHEAD + (d ^ 64)];
        g_k[(((size_t)b * NKVH + h) * NS + s) * DHEAD + d] = v * c + sign * pr * sn;
        g_v[(((size_t)b * NKVH + h) * NS + s) * DHEAD + d] =
            row[NHID + NKVH * DHEAD + h * DHEAD + d];
    }
}

// ------------------------- flash attention (fp32, causal, GQA) -------------
__global__ void __launch_bounds__(256) flash_attn() {
    extern __shared__ float sm[];
    float* Qs = sm;                        // [64][129]
    float* Ks = Qs + 64 * 129;             // [64][129]
    float* Vs = Ks + 64 * 129;             // [64][128]
    float* Ps = Vs + 64 * 128;             // [64][65]

    const int tid = threadIdx.x;
    const int tx = tid & 15;
    const int ty = tid >> 4;
    const int qb = gridDim.x - 1 - blockIdx.x;
    const int h = blockIdx.y;
    const int b = blockIdx.z;
    const int hk = h >> 2;
    const int q0 = qb * 64;

    const float* Qg = g_q + (((size_t)b * NHEADS + h) * NS + q0) * DHEAD;
    const float* Kg = g_k + (((size_t)b * NKVH + hk) * NS) * DHEAD;
    const float* Vg = g_v + (((size_t)b * NKVH + hk) * NS) * DHEAD;

    for (int i = tid; i < 64 * 32; i += 256) {
        int r = i >> 5, cc = (i & 31) * 4;
        float4 q4 = *(const float4*)(Qg + r * DHEAD + cc);
        float* dst = Qs + r * 129 + cc;
        dst[0] = q4.x; dst[1] = q4.y; dst[2] = q4.z; dst[3] = q4.w;
    }

    float m_i[4], l_i[4], acc[4][8];
#pragma unroll
    for (int i = 0; i < 4; i++) {
        m_i[i] = -1e30f;
        l_i[i] = 0.0f;
#pragma unroll
        for (int j = 0; j < 8; j++) acc[i][j] = 0.0f;
    }

    const int ntiles = qb + 1;
    for (int t = 0; t < ntiles; t++) {
        const float* Kt = Kg + (size_t)t * 64 * DHEAD;
        const float* Vt = Vg + (size_t)t * 64 * DHEAD;
        __syncthreads();
        for (int i = tid; i < 64 * 32; i += 256) {
            int r = i >> 5, cc = (i & 31) * 4;
            float4 k4 = *(const float4*)(Kt + r * DHEAD + cc);
            float* kd = Ks + r * 129 + cc;
            kd[0] = k4.x; kd[1] = k4.y; kd[2] = k4.z; kd[3] = k4.w;
            float4 v4 = *(const float4*)(Vt + r * DHEAD + cc);
            *(float4*)(Vs + r * DHEAD + cc) = v4;
        }
        __syncthreads();

        float sc[4][4];
#pragma unroll
        for (int i = 0; i < 4; i++)
#pragma unroll
            for (int j = 0; j < 4; j++) sc[i][j] = 0.0f;

#pragma unroll 4
        for (int k = 0; k < DHEAD; k++) {
            float rq[4], rk[4];
#pragma unroll
            for (int i = 0; i < 4; i++) rq[i] = Qs[(4 * ty + i) * 129 + k];
#pragma unroll
            for (int j = 0; j < 4; j++) rk[j] = Ks[(tx + 16 * j) * 129 + k];
#pragma unroll
            for (int i = 0; i < 4; i++)
#pragma unroll
                for (int j = 0; j < 4; j++) sc[i][j] += rq[i] * rk[j];
        }

        if (t == qb) {
#pragma unroll
            for (int i = 0; i < 4; i++)
#pragma unroll
                for (int j = 0; j < 4; j++)
                    if (tx + 16 * j > 4 * ty + i) sc[i][j] = -1e30f;
        }

#pragma unroll
        for (int i = 0; i < 4; i++) {
            float mx = fmaxf(fmaxf(sc[i][0], sc[i][1]), fmaxf(sc[i][2], sc[i][3]));
            mx = fmaxf(mx, __shfl_xor_sync(0xffffffffu, mx, 1));
            mx = fmaxf(mx, __shfl_xor_sync(0xffffffffu, mx, 2));
            mx = fmaxf(mx, __shfl_xor_sync(0xffffffffu, mx, 4));
            mx = fmaxf(mx, __shfl_xor_sync(0xffffffffu, mx, 8));
            float mnew = fmaxf(m_i[i], mx);
            float scale = __expf(m_i[i] - mnew);
            float rs = 0.0f;
#pragma unroll
            for (int j = 0; j < 4; j++) {
                float pexp = __expf(sc[i][j] - mnew);
                sc[i][j] = pexp;
                rs += pexp;
            }
            rs += __shfl_xor_sync(0xffffffffu, rs, 1);
            rs += __shfl_xor_sync(0xffffffffu, rs, 2);
            rs += __shfl_xor_sync(0xffffffffu, rs, 4);
            rs += __shfl_xor_sync(0xffffffffu, rs, 8);
            l_i[i] = l_i[i] * scale + rs;
            m_i[i] = mnew;
#pragma unroll
            for (int jj = 0; jj < 8; jj++) acc[i][jj] *= scale;
#pragma unroll
            for (int j = 0; j < 4; j++)
                Ps[(4 * ty + i) * 65 + tx + 16 * j] = sc[i][j];
        }
        __syncthreads();

#pragma unroll 4
        for (int j = 0; j < 64; j++) {
            float pv[4];
#pragma unroll
            for (int i = 0; i < 4; i++) pv[i] = Ps[(4 * ty + i) * 65 + j];
#pragma unroll
            for (int jj = 0; jj < 8; jj++) {
                float vv = Vs[j * DHEAD + tx + 16 * jj];
#pragma unroll
                for (int i = 0; i < 4; i++) acc[i][jj] += pv[i] * vv;
            }
        }
    }

#pragma unroll
    for (int i = 0; i < 4; i++) {
        float inv = 1.0f / l_i[i];
        int q = q0 + 4 * ty + i;
        float* outp = g_attn + ((size_t)b * NS + q) * NHID + h * DHEAD;
#pragma unroll
        for (int jj = 0; jj < 8; jj++) outp[tx + 16 * jj] = acc[i][jj] * inv;
    }
}

// ------------------------- launch ------------------------------------------
extern "C" void kernel_launch(void* const* d_in, const int* in_sizes, int n_in,
                              void* d_out, int out_size) {
    const float* hidden = (const float*)d_in[0];
    const void* pos = d_in[1];
    const float* Wqkv = (const float*)d_in[2];
    const float* Wout = (const float*)d_in[3];
    float* out = (float*)d_out;

    void *p_qkv, *p_attn;
    void *p_hh, *p_hl, *p_w1h, *p_w1l, *p_w2h, *p_w2l, *p_ah, *p_al;
    cudaGetSymbolAddress(&p_qkv, g_qkv);
    cudaGetSymbolAddress(&p_attn, g_attn);
    cudaGetSymbolAddress(&p_hh, g_hid_hi);
    cudaGetSymbolAddress(&p_hl, g_hid_lo);
    cudaGetSymbolAddress(&p_w1h, g_w1_hi);
    cudaGetSymbolAddress(&p_w1l, g_w1_lo);
    cudaGetSymbolAddress(&p_w2h, g_w2_hi);
    cudaGetSymbolAddress(&p_w2l, g_w2_lo);
    cudaGetSymbolAddress(&p_ah, g_at_hi);
    cudaGetSymbolAddress(&p_al, g_at_lo);

    const int nHid = NB * NS * NHID;
    const int nW1 = NQKV * NHID;
    const int nW2 = NHID * NHID;

    split_bf16<<<(nHid / 4 + 255) / 256, 256>>>(hidden, (__nv_bfloat16*)p_hh,
                                                (__nv_bfloat16*)p_hl, nHid / 4);
    split_bf16<<<(nW1 / 4 + 255) / 256, 256>>>(Wqkv, (__nv_bfloat16*)p_w1h,
                                               (__nv_bfloat16*)p_w1l, nW1 / 4);
    split_bf16<<<(nW2 / 4 + 255) / 256, 256>>>(Wout, (__nv_bfloat16*)p_w2h,
                                               (__nv_bfloat16*)p_w2l, nW2 / 4);

    // 1) QKV projection + clamp (tensor cores, 3-pass bf16)
    {
        cudaFuncSetAttribute(gemm_hmma<1>, cudaFuncAttributeMaxDynamicSharedMemorySize, GSMEM);
        dim3 grid(NQKV / 128, (NB * NS) / 128);
        gemm_hmma<1><<<grid, 256, GSMEM>>>(
            (const __nv_bfloat16*)p_hh, (const __nv_bfloat16*)p_hl,
            (const __nv_bfloat16*)p_w1h, (const __nv_bfloat16*)p_w1l,
            (float*)p_qkv, NB * NS, NQKV, NHID);
    }
    // 2) RoPE + scatter
    rope_scatter<<<NB * NS, 128>>>(pos);

    // 3) causal flash attention
    {
        const int smem = (64 * 129 + 64 * 129 + 64 * 128 + 64 * 65) * 4;
        cudaFuncSetAttribute(flash_attn, cudaFuncAttributeMaxDynamicSharedMemorySize, smem);
        dim3 grid(NS / 64, NHEADS, NB);
        flash_attn<<<grid, 256, smem>>>();
    }

    // 4) split attention output, then output projection (tensor cores)
    split_bf16<<<(nHid / 4 + 255) / 256, 256>>>((const float*)p_attn, (__nv_bfloat16*)p_ah,
                                                (__nv_bfloat16*)p_al, nHid / 4);
    {
        cudaFuncSetAttribute(gemm_hmma<0>, cudaFuncAttributeMaxDynamicSharedMemorySize, GSMEM);
        dim3 grid(NHID / 128, (NB * NS) / 128);
        gemm_hmma<0><<<grid, 256, GSMEM>>>(
            (const __nv_bfloat16*)p_ah, (const __nv_bfloat16*)p_al,
            (const __nv_bfloat16*)p_w2h, (const __nv_bfloat16*)p_w2l,
            out, NB * NS, NHID, NHID);
    }
}

// round 5
// speedup vs baseline: 2.5359x; 1.5112x over previous
#include <cuda_runtime.h>
#include <cuda_bf16.h>
#include <cstdint>
#include <math.h>

#define NB 2
#define NS 2048
#define NHID 2048
#define NHEADS 16
#define NKVH 4
#define DHEAD 128
#define NQKV 3072

// ------------------------- scratch (static device globals; no allocs) ------
static __device__ float g_qkv[(size_t)NB * NS * NQKV];

static __device__ __nv_bfloat16 g_qh[(size_t)NB * NHEADS * NS * DHEAD];
static __device__ __nv_bfloat16 g_ql[(size_t)NB * NHEADS * NS * DHEAD];
static __device__ __nv_bfloat16 g_kh[(size_t)NB * NKVH * NS * DHEAD];
static __device__ __nv_bfloat16 g_kl[(size_t)NB * NKVH * NS * DHEAD];
static __device__ __nv_bfloat16 g_vth[(size_t)NB * NKVH * DHEAD * NS];  // [b,hk,d,s]
static __device__ __nv_bfloat16 g_vtl[(size_t)NB * NKVH * DHEAD * NS];

static __device__ __nv_bfloat16 g_hid_hi[(size_t)NB * NS * NHID];
static __device__ __nv_bfloat16 g_hid_lo[(size_t)NB * NS * NHID];
static __device__ __nv_bfloat16 g_w1_hi[(size_t)NQKV * NHID];
static __device__ __nv_bfloat16 g_w1_lo[(size_t)NQKV * NHID];
static __device__ __nv_bfloat16 g_w2_hi[(size_t)NHID * NHID];
static __device__ __nv_bfloat16 g_w2_lo[(size_t)NHID * NHID];
static __device__ __nv_bfloat16 g_at_hi[(size_t)NB * NS * NHID];
static __device__ __nv_bfloat16 g_at_lo[(size_t)NB * NS * NHID];

// ------------------------- PTX helpers (baseline ISA only) -----------------
__device__ __forceinline__ uint32_t smem_u32(const void* p) {
    uint32_t a;
    asm("{ .reg .u64 t; cvta.to.shared.u64 t, %1; cvt.u32.u64 %0, t; }"
        : "=r"(a) : "l"(p));
    return a;
}

__device__ __forceinline__ void cp16(uint32_t dst, const void* src) {
    asm volatile("cp.async.cg.shared.global [%0], [%1], 16;"
                 :: "r"(dst), "l"(src));
}
#define CP_COMMIT() asm volatile("cp.async.commit_group;" ::: "memory")
#define CP_WAIT0() asm volatile("cp.async.wait_group 0;" ::: "memory")
#define CP_WAIT1() asm volatile("cp.async.wait_group 1;" ::: "memory")

__device__ __forceinline__ void ldsm4(uint32_t* r, uint32_t addr) {
    asm volatile("ldmatrix.sync.aligned.m8n8.x4.shared.b16 {%0,%1,%2,%3}, [%4];"
                 : "=r"(r[0]), "=r"(r[1]), "=r"(r[2]), "=r"(r[3]) : "r"(addr));
}

__device__ __forceinline__ void mma16816(float* c, const uint32_t* a, const uint32_t* b) {
    asm volatile(
        "mma.sync.aligned.m16n8k16.row.col.f32.bf16.bf16.f32 "
        "{%0,%1,%2,%3}, {%4,%5,%6,%7}, {%8,%9}, {%0,%1,%2,%3};"
        : "+f"(c[0]), "+f"(c[1]), "+f"(c[2]), "+f"(c[3])
        : "r"(a[0]), "r"(a[1]), "r"(a[2]), "r"(a[3]), "r"(b[0]), "r"(b[1]));
}

__device__ __forceinline__ void bsplit(float x, __nv_bfloat16& h, __nv_bfloat16& l) {
    h = __float2bfloat16(x);
    l = __float2bfloat16(x - __bfloat162float(h));
}

__device__ __forceinline__ void split_pack2(float a, float b, uint32_t& hi, uint32_t& lo) {
    __nv_bfloat16 ah, al, bh, bl;
    bsplit(a, ah, al);
    bsplit(b, bh, bl);
    hi = (uint32_t)__bfloat16_as_ushort(ah) | ((uint32_t)__bfloat16_as_ushort(bh) << 16);
    lo = (uint32_t)__bfloat16_as_ushort(al) | ((uint32_t)__bfloat16_as_ushort(bl) << 16);
}

// ------------------------- split fp32 -> bf16 hi/lo ------------------------
__global__ void __launch_bounds__(256) split_bf16(const float* __restrict__ x,
                                                  __nv_bfloat16* __restrict__ hi,
                                                  __nv_bfloat16* __restrict__ lo,
                                                  int n4) {
    int i = blockIdx.x * 256 + threadIdx.x;
    if (i >= n4) return;
    float4 v = ((const float4*)x)[i];
    __nv_bfloat16 h0, l0, h1, l1, h2, l2, h3, l3;
    bsplit(v.x, h0, l0); bsplit(v.y, h1, l1);
    bsplit(v.z, h2, l2); bsplit(v.w, h3, l3);
    __nv_bfloat162 hh0 = {h0, h1}, hh1 = {h2, h3};
    __nv_bfloat162 ll0 = {l0, l1}, ll1 = {l2, l3};
    ((__nv_bfloat162*)hi)[2 * i] = hh0;
    ((__nv_bfloat162*)hi)[2 * i + 1] = hh1;
    ((__nv_bfloat162*)lo)[2 * i] = ll0;
    ((__nv_bfloat162*)lo)[2 * i + 1] = ll1;
}

// ------------------------- HMMA GEMM: C[M,N] = A[M,K] * B[N,K]^T -----------
#define ROWB 80
#define OPSZ (128 * ROWB)
#define STAGESZ (4 * OPSZ)
#define GSMEM (2 * STAGESZ)

template <int CLAMP>
__global__ void __launch_bounds__(256) gemm_hmma(const __nv_bfloat16* __restrict__ Ahi,
                                                 const __nv_bfloat16* __restrict__ Alo,
                                                 const __nv_bfloat16* __restrict__ Bhi,
                                                 const __nv_bfloat16* __restrict__ Blo,
                                                 float* __restrict__ C,
                                                 int M, int N, int K) {
    extern __shared__ char smem[];
    const uint32_t sb = smem_u32(smem);
    const int tid = threadIdx.x;
    const int lane = tid & 31;
    const int wid = tid >> 5;
    const int wm = (wid & 1) * 64;
    const int wn = (wid >> 1) * 32;
    const int bx = blockIdx.x;
    const int by = blockIdx.y;

    const int r0 = tid >> 2, c0 = (tid & 3);
    const int r1 = (tid + 256) >> 2, c1 = tid & 3;

    const __nv_bfloat16* gA[2] = {Ahi, Alo};
    const __nv_bfloat16* gB[2] = {Bhi, Blo};

    auto load_stage = [&](int stage, int kt) {
        const uint32_t s = sb + stage * STAGESZ;
        const int kc = kt * 32;
#pragma unroll
        for (int hl = 0; hl < 2; hl++) {
            const __nv_bfloat16* A = gA[hl] + (size_t)(by * 128) * K + kc;
            const __nv_bfloat16* B = gB[hl] + (size_t)(bx * 128) * K + kc;
            const uint32_t sA = s + hl * OPSZ;
            const uint32_t sB = s + (2 + hl) * OPSZ;
            cp16(sA + r0 * ROWB + c0 * 16, A + (size_t)r0 * K + c0 * 8);
            cp16(sA + r1 * ROWB + c1 * 16, A + (size_t)r1 * K + c1 * 8);
            cp16(sB + r0 * ROWB + c0 * 16, B + (size_t)r0 * K + c0 * 8);
            cp16(sB + r1 * ROWB + c1 * 16, B + (size_t)r1 * K + c1 * 8);
        }
    };

    float acc[4][4][4];
#pragma unroll
    for (int i = 0; i < 4; i++)
#pragma unroll
        for (int j = 0; j < 4; j++)
#pragma unroll
            for (int e = 0; e < 4; e++) acc[i][j][e] = 0.0f;

    const int KT = K >> 5;
    load_stage(0, 0);
    CP_COMMIT();

    const int lrow = (lane & 7) + ((lane >> 3) & 1) * 8;
    const int lchunk = lane >> 4;

    for (int kt = 0; kt < KT; kt++) {
        if (kt + 1 < KT) {
            load_stage((kt + 1) & 1, kt + 1);
            CP_COMMIT();
            CP_WAIT1();
        } else {
            CP_WAIT0();
        }
        __syncthreads();

        const uint32_t s = sb + (kt & 1) * STAGESZ;
#pragma unroll
        for (int ks = 0; ks < 2; ks++) {
            const int cb = 2 * ks;
            uint32_t ah[4][4], al[4][4], bh[4][2], bl[4][2];
#pragma unroll
            for (int mf = 0; mf < 4; mf++) {
                const uint32_t ra = (wm + mf * 16 + lrow) * ROWB + (cb + lchunk) * 16;
                ldsm4(ah[mf], s + ra);
                ldsm4(al[mf], s + OPSZ + ra);
            }
#pragma unroll
            for (int nf2 = 0; nf2 < 2; nf2++) {
                const uint32_t rb = (wn + nf2 * 16 + lrow) * ROWB + (cb + lchunk) * 16;
                uint32_t th[4], tl[4];
                ldsm4(th, s + 2 * OPSZ + rb);
                ldsm4(tl, s + 3 * OPSZ + rb);
                bh[nf2 * 2][0] = th[0]; bh[nf2 * 2 + 1][0] = th[1];
                bh[nf2 * 2][1] = th[2]; bh[nf2 * 2 + 1][1] = th[3];
                bl[nf2 * 2][0] = tl[0]; bl[nf2 * 2 + 1][0] = tl[1];
                bl[nf2 * 2][1] = tl[2]; bl[nf2 * 2 + 1][1] = tl[3];
            }
#pragma unroll
            for (int mf = 0; mf < 4; mf++)
#pragma unroll
                for (int nf = 0; nf < 4; nf++) {
                    mma16816(acc[mf][nf], ah[mf], bh[nf]);
                    mma16816(acc[mf][nf], ah[mf], bl[nf]);
                    mma16816(acc[mf][nf], al[mf], bh[nf]);
                }
        }
        __syncthreads();
    }

    const int erow = lane >> 2;
    const int ecol = (lane & 3) * 2;
#pragma unroll
    for (int mf = 0; mf < 4; mf++) {
#pragma unroll
        for (int nf = 0; nf < 4; nf++) {
            float* c = acc[mf][nf];
            if (CLAMP) {
#pragma unroll
                for (int e = 0; e < 4; e++)
                    c[e] = fminf(8.0f, fmaxf(-8.0f, c[e]));
            }
            const int row = by * 128 + wm + mf * 16 + erow;
            const int col = bx * 128 + wn + nf * 8 + ecol;
            float2 v0 = {c[0], c[1]};
            float2 v1 = {c[2], c[3]};
            *(float2*)(C + (size_t)row * N + col) = v0;
            *(float2*)(C + (size_t)(row + 8) * N + col) = v1;
        }
    }
}

// ------------------------- RoPE + scatter to bf16 hi/lo --------------------
__global__ void __launch_bounds__(128) rope_scatter(const void* __restrict__ pos_ids) {
    const int bs = blockIdx.x;
    const int b = bs / NS;
    const int s = bs % NS;
    const int d = threadIdx.x;
    const int dm = d & 63;

    const int* p32 = (const int*)pos_ids;
    const bool is64 = (p32[1] == 0) && (p32[3] == 0) && (p32[2 * NS + 1] == 0);
    const long long pv = is64 ? ((const long long*)pos_ids)[bs] : (long long)p32[bs];

    const double p = (double)pv;
    const double invf = pow(500000.0, -(double)dm / 64.0);
    double sd, cd;
    sincos(p * invf, &sd, &cd);
    const float c = (float)cd;
    const float sn = (float)sd;
    const float sign = (d < 64) ? -1.0f : 1.0f;
    const float qscale = 0.08838834764831845f;

    const float* row = g_qkv + (size_t)bs * NQKV;

#pragma unroll
    for (int h = 0; h < NHEADS; h++) {
        float v = row[h * DHEAD + d];
        float pr = row[h * DHEAD + (d ^ 64)];
        float qv = (v * c + sign * pr * sn) * qscale;
        __nv_bfloat16 hh, ll;
        bsplit(qv, hh, ll);
        size_t idx = (((size_t)b * NHEADS + h) * NS + s) * DHEAD + d;
        g_qh[idx] = hh;
        g_ql[idx] = ll;
    }
#pragma unroll
    for (int h = 0; h < NKVH; h++) {
        float v = row[NHID + h * DHEAD + d];
        float pr = row[NHID + h * DHEAD + (d ^ 64)];
        float kv = v * c + sign * pr * sn;
        __nv_bfloat16 hh, ll;
        bsplit(kv, hh, ll);
        size_t idx = (((size_t)b * NKVH + h) * NS + s) * DHEAD + d;
        g_kh[idx] = hh;
        g_kl[idx] = ll;
        float vv = row[NHID + NKVH * DHEAD + h * DHEAD + d];
        bsplit(vv, hh, ll);
        size_t vidx = (((size_t)b * NKVH + h) * DHEAD + d) * NS + s;
        g_vth[vidx] = hh;
        g_vtl[vidx] = ll;
    }
}

// ------------------------- tensor-core flash attention ---------------------
// BM=64, BN=64, 4 warps. bf16 hi/lo 3-pass for QK^T and PV. fp32 softmax.
// smem rows: Q/K padded to 272B (17 slots), Vt to 144B (9 slots).
#define AQ_HI 0
#define AQ_LO (64 * 272)
#define AK_HI (2 * 64 * 272)
#define AK_LO (3 * 64 * 272)
#define AVT_HI (4 * 64 * 272)
#define AVT_LO (4 * 64 * 272 + 128 * 144)
#define ATTN_SMEM (4 * 64 * 272 + 2 * 128 * 144)  // 106496

__global__ void __launch_bounds__(128) flash_attn_tc() {
    extern __shared__ char smem[];
    const uint32_t sb = smem_u32(smem);
    const int tid = threadIdx.x;
    const int lane = tid & 31;
    const int w = tid >> 5;
    const int qb = gridDim.x - 1 - blockIdx.x;
    const int h = blockIdx.y;
    const int b = blockIdx.z;
    const int hk = h >> 2;
    const int q0 = qb * 64;
    const int wrow = w * 16;

    const __nv_bfloat16* Qh = g_qh + ((size_t)(b * NHEADS + h) * NS + q0) * DHEAD;
    const __nv_bfloat16* Ql = g_ql + ((size_t)(b * NHEADS + h) * NS + q0) * DHEAD;
    const __nv_bfloat16* Kh = g_kh + ((size_t)(b * NKVH + hk) * NS) * DHEAD;
    const __nv_bfloat16* Kl = g_kl + ((size_t)(b * NKVH + hk) * NS) * DHEAD;
    const __nv_bfloat16* Vth = g_vth + ((size_t)(b * NKVH + hk) * DHEAD) * NS;
    const __nv_bfloat16* Vtl = g_vtl + ((size_t)(b * NKVH + hk) * DHEAD) * NS;

    // load Q tile (64 x 128, hi+lo)
#pragma unroll
    for (int i = 0; i < 8; i++) {
        int q = tid + i * 128;
        int r = q >> 4, cc = q & 15;
        cp16(sb + AQ_HI + r * 272 + cc * 16, Qh + (size_t)r * DHEAD + cc * 8);
        cp16(sb + AQ_LO + r * 272 + cc * 16, Ql + (size_t)r * DHEAD + cc * 8);
    }
    CP_COMMIT();

    float of[16][4];
#pragma unroll
    for (int f = 0; f < 16; f++)
#pragma unroll
        for (int e = 0; e < 4; e++) of[f][e] = 0.0f;
    float m0 = -1e30f, m1 = -1e30f, l0 = 0.0f, l1 = 0.0f;

    const int lr = (lane & 7) + ((lane >> 3) & 1) * 8;
    const int lc16 = (lane >> 4) * 16;

    for (int t = 0; t <= qb; t++) {
        __syncthreads();
#pragma unroll
        for (int i = 0; i < 8; i++) {
            int q = tid + i * 128;
            int r = q >> 4, cc = q & 15;
            cp16(sb + AK_HI + r * 272 + cc * 16, Kh + (size_t)(t * 64 + r) * DHEAD + cc * 8);
            cp16(sb + AK_LO + r * 272 + cc * 16, Kl + (size_t)(t * 64 + r) * DHEAD + cc * 8);
        }
#pragma unroll
        for (int i = 0; i < 8; i++) {
            int q = tid + i * 128;
            int d = q >> 3, cc = q & 7;
            cp16(sb + AVT_HI + d * 144 + cc * 16, Vth + (size_t)d * NS + t * 64 + cc * 8);
            cp16(sb + AVT_LO + d * 144 + cc * 16, Vtl + (size_t)d * NS + t * 64 + cc * 8);
        }
        CP_COMMIT();
        CP_WAIT0();
        __syncthreads();

        // S = Q K^T : 16 rows x 64 cols per warp
        float sc[8][4];
#pragma unroll
        for (int nf = 0; nf < 8; nf++)
#pragma unroll
            for (int e = 0; e < 4; e++) sc[nf][e] = 0.0f;

#pragma unroll
        for (int kc = 0; kc < 8; kc++) {
            uint32_t qh4[4], ql4[4];
            const uint32_t qaddr = sb + AQ_HI + (wrow + lr) * 272 + kc * 32 + lc16;
            ldsm4(qh4, qaddr);
            ldsm4(ql4, qaddr + (AQ_LO - AQ_HI));
#pragma unroll
            for (int np = 0; np < 4; np++) {
                uint32_t kh4[4], kl4[4];
                const uint32_t kaddr = sb + AK_HI + (np * 16 + lr) * 272 + kc * 32 + lc16;
                ldsm4(kh4, kaddr);
                ldsm4(kl4, kaddr + (AK_LO - AK_HI));
                uint32_t bh0[2] = {kh4[0], kh4[2]}, bh1[2] = {kh4[1], kh4[3]};
                uint32_t bl0[2] = {kl4[0], kl4[2]}, bl1[2] = {kl4[1], kl4[3]};
                mma16816(sc[2 * np], qh4, bh0);
                mma16816(sc[2 * np], qh4, bl0);
                mma16816(sc[2 * np], ql4, bh0);
                mma16816(sc[2 * np + 1], qh4, bh1);
                mma16816(sc[2 * np + 1], qh4, bl1);
                mma16816(sc[2 * np + 1], ql4, bh1);
            }
        }

        if (t == qb) {  // causal mask on diagonal tile
            const int row0 = q0 + wrow + (lane >> 2);
            const int colb = t * 64 + 2 * (lane & 3);
#pragma unroll
            for (int nf = 0; nf < 8; nf++) {
                const int cb = colb + 8 * nf;
                if (cb > row0) sc[nf][0] = -1e30f;
                if (cb + 1 > row0) sc[nf][1] = -1e30f;
                if (cb > row0 + 8) sc[nf][2] = -1e30f;
                if (cb + 1 > row0 + 8) sc[nf][3] = -1e30f;
            }
        }

        // online softmax (rows r=lane/4 and r+8)
        float rmax0 = -1e30f, rmax1 = -1e30f;
#pragma unroll
        for (int nf = 0; nf < 8; nf++) {
            rmax0 = fmaxf(rmax0, fmaxf(sc[nf][0], sc[nf][1]));
            rmax1 = fmaxf(rmax1, fmaxf(sc[nf][2], sc[nf][3]));
        }
        rmax0 = fmaxf(rmax0, __shfl_xor_sync(0xffffffffu, rmax0, 1));
        rmax0 = fmaxf(rmax0, __shfl_xor_sync(0xffffffffu, rmax0, 2));
        rmax1 = fmaxf(rmax1, __shfl_xor_sync(0xffffffffu, rmax1, 1));
        rmax1 = fmaxf(rmax1, __shfl_xor_sync(0xffffffffu, rmax1, 2));
        const float mn0 = fmaxf(m0, rmax0);
        const float mn1 = fmaxf(m1, rmax1);
        const float scl0 = __expf(m0 - mn0);
        const float scl1 = __expf(m1 - mn1);
        float rs0 = 0.0f, rs1 = 0.0f;
#pragma unroll
        for (int nf = 0; nf < 8; nf++) {
            sc[nf][0] = __expf(sc[nf][0] - mn0); rs0 += sc[nf][0];
            sc[nf][1] = __expf(sc[nf][1] - mn0); rs0 += sc[nf][1];
            sc[nf][2] = __expf(sc[nf][2] - mn1); rs1 += sc[nf][2];
            sc[nf][3] = __expf(sc[nf][3] - mn1); rs1 += sc[nf][3];
        }
        rs0 += __shfl_xor_sync(0xffffffffu, rs0, 1);
        rs0 += __shfl_xor_sync(0xffffffffu, rs0, 2);
        rs1 += __shfl_xor_sync(0xffffffffu, rs1, 1);
        rs1 += __shfl_xor_sync(0xffffffffu, rs1, 2);
        l0 = l0 * scl0 + rs0;
        l1 = l1 * scl1 + rs1;
        m0 = mn0;
        m1 = mn1;
#pragma unroll
        for (int f = 0; f < 16; f++) {
            of[f][0] *= scl0; of[f][1] *= scl0;
            of[f][2] *= scl1; of[f][3] *= scl1;
        }

        // O += P V  (P frags reuse S accumulator layout)
#pragma unroll
        for (int kb = 0; kb < 4; kb++) {
            uint32_t ph[4], pl[4];
            split_pack2(sc[2 * kb][0], sc[2 * kb][1], ph[0], pl[0]);
            split_pack2(sc[2 * kb][2], sc[2 * kb][3], ph[1], pl[1]);
            split_pack2(sc[2 * kb + 1][0], sc[2 * kb + 1][1], ph[2], pl[2]);
            split_pack2(sc[2 * kb + 1][2], sc[2 * kb + 1][3], ph[3], pl[3]);
#pragma unroll
            for (int np = 0; np < 8; np++) {
                uint32_t vh4[4], vl4[4];
                const uint32_t vaddr = sb + AVT_HI + (np * 16 + lr) * 144 + kb * 32 + lc16;
                ldsm4(vh4, vaddr);
                ldsm4(vl4, vaddr + (AVT_LO - AVT_HI));
                uint32_t bh0[2] = {vh4[0], vh4[2]}, bh1[2] = {vh4[1], vh4[3]};
                uint32_t bl0[2] = {vl4[0], vl4[2]}, bl1[2] = {vl4[1], vl4[3]};
                mma16816(of[2 * np], ph, bh0);
                mma16816(of[2 * np], ph, bl0);
                mma16816(of[2 * np], pl, bh0);
                mma16816(of[2 * np + 1], ph, bh1);
                mma16816(of[2 * np + 1], ph, bl1);
                mma16816(of[2 * np + 1], pl, bh1);
            }
        }
    }

    // epilogue: O /= l, split to bf16 hi/lo, write head-major
    const float inv0 = 1.0f / l0;
    const float inv1 = 1.0f / l1;
    const int r0g = q0 + wrow + (lane >> 2);
    const int colb = 2 * (lane & 3);
#pragma unroll
    for (int nf = 0; nf < 16; nf++) {
        const int col = h * DHEAD + 8 * nf + colb;
        float x0 = of[nf][0] * inv0, y0 = of[nf][1] * inv0;
        float x1 = of[nf][2] * inv1, y1 = of[nf][3] * inv1;
        __nv_bfloat16 xh, xl, yh, yl;
        bsplit(x0, xh, xl); bsplit(y0, yh, yl);
        size_t i0 = (size_t)(b * NS + r0g) * NHID + col;
        *(__nv_bfloat162*)(g_at_hi + i0) = {xh, yh};
        *(__nv_bfloat162*)(g_at_lo + i0) = {xl, yl};
        bsplit(x1, xh, xl); bsplit(y1, yh, yl);
        size_t i1 = (size_t)(b * NS + r0g + 8) * NHID + col;
        *(__nv_bfloat162*)(g_at_hi + i1) = {xh, yh};
        *(__nv_bfloat162*)(g_at_lo + i1) = {xl, yl};
    }
}

// ------------------------- launch ------------------------------------------
extern "C" void kernel_launch(void* const* d_in, const int* in_sizes, int n_in,
                              void* d_out, int out_size) {
    const float* hidden = (const float*)d_in[0];
    const void* pos = d_in[1];
    const float* Wqkv = (const float*)d_in[2];
    const float* Wout = (const float*)d_in[3];
    float* out = (float*)d_out;

    void *p_qkv, *p_hh, *p_hl, *p_w1h, *p_w1l, *p_w2h, *p_w2l, *p_ah, *p_al;
    cudaGetSymbolAddress(&p_qkv, g_qkv);
    cudaGetSymbolAddress(&p_hh, g_hid_hi);
    cudaGetSymbolAddress(&p_hl, g_hid_lo);
    cudaGetSymbolAddress(&p_w1h, g_w1_hi);
    cudaGetSymbolAddress(&p_w1l, g_w1_lo);
    cudaGetSymbolAddress(&p_w2h, g_w2_hi);
    cudaGetSymbolAddress(&p_w2l, g_w2_lo);
    cudaGetSymbolAddress(&p_ah, g_at_hi);
    cudaGetSymbolAddress(&p_al, g_at_lo);

    const int nHid = NB * NS * NHID;
    const int nW1 = NQKV * NHID;
    const int nW2 = NHID * NHID;

    split_bf16<<<(nHid / 4 + 255) / 256, 256>>>(hidden, (__nv_bfloat16*)p_hh,
                                                (__nv_bfloat16*)p_hl, nHid / 4);
    split_bf16<<<(nW1 / 4 + 255) / 256, 256>>>(Wqkv, (__nv_bfloat16*)p_w1h,
                                               (__nv_bfloat16*)p_w1l, nW1 / 4);
    split_bf16<<<(nW2 / 4 + 255) / 256, 256>>>(Wout, (__nv_bfloat16*)p_w2h,
                                               (__nv_bfloat16*)p_w2l, nW2 / 4);

    // 1) QKV projection + clamp
    {
        cudaFuncSetAttribute(gemm_hmma<1>, cudaFuncAttributeMaxDynamicSharedMemorySize, GSMEM);
        dim3 grid(NQKV / 128, (NB * NS) / 128);
        gemm_hmma<1><<<grid, 256, GSMEM>>>(
            (const __nv_bfloat16*)p_hh, (const __nv_bfloat16*)p_hl,
            (const __nv_bfloat16*)p_w1h, (const __nv_bfloat16*)p_w1l,
            (float*)p_qkv, NB * NS, NQKV, NHID);
    }
    // 2) RoPE + scatter (emits bf16 hi/lo Q, K, V^T)
    rope_scatter<<<NB * NS, 128>>>(pos);

    // 3) tensor-core causal flash attention
    {
        cudaFuncSetAttribute(flash_attn_tc, cudaFuncAttributeMaxDynamicSharedMemorySize, ATTN_SMEM);
        dim3 grid(NS / 64, NHEADS, NB);
        flash_attn_tc<<<grid, 128, ATTN_SMEM>>>();
    }
    // 4) output projection
    {
        cudaFuncSetAttribute(gemm_hmma<0>, cudaFuncAttributeMaxDynamicSharedMemorySize, GSMEM);
        dim3 grid(NHID / 128, (NB * NS) / 128);
        gemm_hmma<0><<<grid, 256, GSMEM>>>(
            (const __nv_bfloat16*)p_ah, (const __nv_bfloat16*)p_al,
            (const __nv_bfloat16*)p_w2h, (const __nv_bfloat16*)p_w2l,
            out, NB * NS, NHID, NHID);
    }
}

// round 6
// speedup vs baseline: 2.6770x; 1.0556x over previous
#include <cuda_runtime.h>
#include <cuda_bf16.h>
#include <cstdint>
#include <math.h>

#define NB 2
#define NS 2048
#define NHID 2048
#define NHEADS 16
#define NKVH 4
#define DHEAD 128
#define NQKV 3072

// ------------------------- scratch (static device globals; no allocs) ------
static __device__ float g_qkv[(size_t)NB * NS * NQKV];

static __device__ __nv_bfloat16 g_qh[(size_t)NB * NHEADS * NS * DHEAD];
static __device__ __nv_bfloat16 g_ql[(size_t)NB * NHEADS * NS * DHEAD];
static __device__ __nv_bfloat16 g_kh[(size_t)NB * NKVH * NS * DHEAD];
static __device__ __nv_bfloat16 g_kl[(size_t)NB * NKVH * NS * DHEAD];
static __device__ __nv_bfloat16 g_vth[(size_t)NB * NKVH * DHEAD * NS];  // [b,hk,d,s]
static __device__ __nv_bfloat16 g_vtl[(size_t)NB * NKVH * DHEAD * NS];

static __device__ __nv_bfloat16 g_hid_hi[(size_t)NB * NS * NHID];
static __device__ __nv_bfloat16 g_hid_lo[(size_t)NB * NS * NHID];
static __device__ __nv_bfloat16 g_w1_hi[(size_t)NQKV * NHID];
static __device__ __nv_bfloat16 g_w1_lo[(size_t)NQKV * NHID];
static __device__ __nv_bfloat16 g_w2_hi[(size_t)NHID * NHID];
static __device__ __nv_bfloat16 g_w2_lo[(size_t)NHID * NHID];
static __device__ __nv_bfloat16 g_at_hi[(size_t)NB * NS * NHID];
static __device__ __nv_bfloat16 g_at_lo[(size_t)NB * NS * NHID];

// ------------------------- PTX helpers (baseline ISA only) -----------------
__device__ __forceinline__ uint32_t smem_u32(const void* p) {
    uint32_t a;
    asm("{ .reg .u64 t; cvta.to.shared.u64 t, %1; cvt.u32.u64 %0, t; }"
        : "=r"(a) : "l"(p));
    return a;
}

__device__ __forceinline__ void cp16(uint32_t dst, const void* src) {
    asm volatile("cp.async.cg.shared.global [%0], [%1], 16;"
                 :: "r"(dst), "l"(src));
}
#define CP_COMMIT() asm volatile("cp.async.commit_group;" ::: "memory")
#define CP_WAIT0() asm volatile("cp.async.wait_group 0;" ::: "memory")
#define CP_WAIT1() asm volatile("cp.async.wait_group 1;" ::: "memory")
#define CP_WAIT2() asm volatile("cp.async.wait_group 2;" ::: "memory")

__device__ __forceinline__ void ldsm4(uint32_t* r, uint32_t addr) {
    asm volatile("ldmatrix.sync.aligned.m8n8.x4.shared.b16 {%0,%1,%2,%3}, [%4];"
                 : "=r"(r[0]), "=r"(r[1]), "=r"(r[2]), "=r"(r[3]) : "r"(addr));
}

__device__ __forceinline__ void mma16816(float* c, const uint32_t* a, const uint32_t* b) {
    asm volatile(
        "mma.sync.aligned.m16n8k16.row.col.f32.bf16.bf16.f32 "
        "{%0,%1,%2,%3}, {%4,%5,%6,%7}, {%8,%9}, {%0,%1,%2,%3};"
        : "+f"(c[0]), "+f"(c[1]), "+f"(c[2]), "+f"(c[3])
        : "r"(a[0]), "r"(a[1]), "r"(a[2]), "r"(a[3]), "r"(b[0]), "r"(b[1]));
}

__device__ __forceinline__ void bsplit(float x, __nv_bfloat16& h, __nv_bfloat16& l) {
    h = __float2bfloat16(x);
    l = __float2bfloat16(x - __bfloat162float(h));
}

__device__ __forceinline__ void split_pack2(float a, float b, uint32_t& hi, uint32_t& lo) {
    __nv_bfloat16 ah, al, bh, bl;
    bsplit(a, ah, al);
    bsplit(b, bh, bl);
    hi = (uint32_t)__bfloat16_as_ushort(ah) | ((uint32_t)__bfloat16_as_ushort(bh) << 16);
    lo = (uint32_t)__bfloat16_as_ushort(al) | ((uint32_t)__bfloat16_as_ushort(bl) << 16);
}

// ------------------------- split fp32 -> bf16 hi/lo ------------------------
__global__ void __launch_bounds__(256) split_bf16(const float* __restrict__ x,
                                                  __nv_bfloat16* __restrict__ hi,
                                                  __nv_bfloat16* __restrict__ lo,
                                                  int n4) {
    int i = blockIdx.x * 256 + threadIdx.x;
    if (i >= n4) return;
    float4 v = ((const float4*)x)[i];
    __nv_bfloat16 h0, l0, h1, l1, h2, l2, h3, l3;
    bsplit(v.x, h0, l0); bsplit(v.y, h1, l1);
    bsplit(v.z, h2, l2); bsplit(v.w, h3, l3);
    __nv_bfloat162 hh0 = {h0, h1}, hh1 = {h2, h3};
    __nv_bfloat162 ll0 = {l0, l1}, ll1 = {l2, l3};
    ((__nv_bfloat162*)hi)[2 * i] = hh0;
    ((__nv_bfloat162*)hi)[2 * i + 1] = hh1;
    ((__nv_bfloat162*)lo)[2 * i] = ll0;
    ((__nv_bfloat162*)lo)[2 * i + 1] = ll1;
}

// ------------------------- HMMA GEMM: C[M,N] = A[M,K] * B[N,K]^T -----------
#define ROWB 80
#define OPSZ (128 * ROWB)
#define STAGESZ (4 * OPSZ)
#define GSMEM (2 * STAGESZ)

template <int CLAMP>
__global__ void __launch_bounds__(256) gemm_hmma(const __nv_bfloat16* __restrict__ Ahi,
                                                 const __nv_bfloat16* __restrict__ Alo,
                                                 const __nv_bfloat16* __restrict__ Bhi,
                                                 const __nv_bfloat16* __restrict__ Blo,
                                                 float* __restrict__ C,
                                                 int M, int N, int K) {
    extern __shared__ char smem[];
    const uint32_t sb = smem_u32(smem);
    const int tid = threadIdx.x;
    const int lane = tid & 31;
    const int wid = tid >> 5;
    const int wm = (wid & 1) * 64;
    const int wn = (wid >> 1) * 32;
    const int bx = blockIdx.x;
    const int by = blockIdx.y;

    const int r0 = tid >> 2, c0 = (tid & 3);
    const int r1 = (tid + 256) >> 2, c1 = tid & 3;

    const __nv_bfloat16* gA[2] = {Ahi, Alo};
    const __nv_bfloat16* gB[2] = {Bhi, Blo};

    auto load_stage = [&](int stage, int kt) {
        const uint32_t s = sb + stage * STAGESZ;
        const int kc = kt * 32;
#pragma unroll
        for (int hl = 0; hl < 2; hl++) {
            const __nv_bfloat16* A = gA[hl] + (size_t)(by * 128) * K + kc;
            const __nv_bfloat16* B = gB[hl] + (size_t)(bx * 128) * K + kc;
            const uint32_t sA = s + hl * OPSZ;
            const uint32_t sB = s + (2 + hl) * OPSZ;
            cp16(sA + r0 * ROWB + c0 * 16, A + (size_t)r0 * K + c0 * 8);
            cp16(sA + r1 * ROWB + c1 * 16, A + (size_t)r1 * K + c1 * 8);
            cp16(sB + r0 * ROWB + c0 * 16, B + (size_t)r0 * K + c0 * 8);
            cp16(sB + r1 * ROWB + c1 * 16, B + (size_t)r1 * K + c1 * 8);
        }
    };

    float acc[4][4][4];
#pragma unroll
    for (int i = 0; i < 4; i++)
#pragma unroll
        for (int j = 0; j < 4; j++)
#pragma unroll
            for (int e = 0; e < 4; e++) acc[i][j][e] = 0.0f;

    const int KT = K >> 5;
    load_stage(0, 0);
    CP_COMMIT();

    const int lrow = (lane & 7) + ((lane >> 3) & 1) * 8;
    const int lchunk = lane >> 4;

    for (int kt = 0; kt < KT; kt++) {
        if (kt + 1 < KT) {
            load_stage((kt + 1) & 1, kt + 1);
            CP_COMMIT();
            CP_WAIT1();
        } else {
            CP_WAIT0();
        }
        __syncthreads();

        const uint32_t s = sb + (kt & 1) * STAGESZ;
#pragma unroll
        for (int ks = 0; ks < 2; ks++) {
            const int cb = 2 * ks;
            uint32_t ah[4][4], al[4][4], bh[4][2], bl[4][2];
#pragma unroll
            for (int mf = 0; mf < 4; mf++) {
                const uint32_t ra = (wm + mf * 16 + lrow) * ROWB + (cb + lchunk) * 16;
                ldsm4(ah[mf], s + ra);
                ldsm4(al[mf], s + OPSZ + ra);
            }
#pragma unroll
            for (int nf2 = 0; nf2 < 2; nf2++) {
                const uint32_t rb = (wn + nf2 * 16 + lrow) * ROWB + (cb + lchunk) * 16;
                uint32_t th[4], tl[4];
                ldsm4(th, s + 2 * OPSZ + rb);
                ldsm4(tl, s + 3 * OPSZ + rb);
                bh[nf2 * 2][0] = th[0]; bh[nf2 * 2 + 1][0] = th[1];
                bh[nf2 * 2][1] = th[2]; bh[nf2 * 2 + 1][1] = th[3];
                bl[nf2 * 2][0] = tl[0]; bl[nf2 * 2 + 1][0] = tl[1];
                bl[nf2 * 2][1] = tl[2]; bl[nf2 * 2 + 1][1] = tl[3];
            }
#pragma unroll
            for (int mf = 0; mf < 4; mf++)
#pragma unroll
                for (int nf = 0; nf < 4; nf++) {
                    mma16816(acc[mf][nf], ah[mf], bh[nf]);
                    mma16816(acc[mf][nf], ah[mf], bl[nf]);
                    mma16816(acc[mf][nf], al[mf], bh[nf]);
                }
        }
        __syncthreads();
    }

    const int erow = lane >> 2;
    const int ecol = (lane & 3) * 2;
#pragma unroll
    for (int mf = 0; mf < 4; mf++) {
#pragma unroll
        for (int nf = 0; nf < 4; nf++) {
            float* c = acc[mf][nf];
            if (CLAMP) {
#pragma unroll
                for (int e = 0; e < 4; e++)
                    c[e] = fminf(8.0f, fmaxf(-8.0f, c[e]));
            }
            const int row = by * 128 + wm + mf * 16 + erow;
            const int col = bx * 128 + wn + nf * 8 + ecol;
            float2 v0 = {c[0], c[1]};
            float2 v1 = {c[2], c[3]};
            *(float2*)(C + (size_t)row * N + col) = v0;
            *(float2*)(C + (size_t)(row + 8) * N + col) = v1;
        }
    }
}

// ------------------------- RoPE + scatter to bf16 hi/lo --------------------
__global__ void __launch_bounds__(128) rope_scatter(const void* __restrict__ pos_ids) {
    const int bs = blockIdx.x;
    const int b = bs / NS;
    const int s = bs % NS;
    const int d = threadIdx.x;
    const int dm = d & 63;

    const int* p32 = (const int*)pos_ids;
    const bool is64 = (p32[1] == 0) && (p32[3] == 0) && (p32[2 * NS + 1] == 0);
    const long long pv = is64 ? ((const long long*)pos_ids)[bs] : (long long)p32[bs];

    const double p = (double)pv;
    const double invf = pow(500000.0, -(double)dm / 64.0);
    double sd, cd;
    sincos(p * invf, &sd, &cd);
    const float c = (float)cd;
    const float sn = (float)sd;
    const float sign = (d < 64) ? -1.0f : 1.0f;
    const float qscale = 0.08838834764831845f;

    const float* row = g_qkv + (size_t)bs * NQKV;

#pragma unroll
    for (int h = 0; h < NHEADS; h++) {
        float v = row[h * DHEAD + d];
        float pr = row[h * DHEAD + (d ^ 64)];
        float qv = (v * c + sign * pr * sn) * qscale;
        __nv_bfloat16 hh, ll;
        bsplit(qv, hh, ll);
        size_t idx = (((size_t)b * NHEADS + h) * NS + s) * DHEAD + d;
        g_qh[idx] = hh;
        g_ql[idx] = ll;
    }
#pragma unroll
    for (int h = 0; h < NKVH; h++) {
        float v = row[NHID + h * DHEAD + d];
        float pr = row[NHID + h * DHEAD + (d ^ 64)];
        float kv = v * c + sign * pr * sn;
        __nv_bfloat16 hh, ll;
        bsplit(kv, hh, ll);
        size_t idx = (((size_t)b * NKVH + h) * NS + s) * DHEAD + d;
        g_kh[idx] = hh;
        g_kl[idx] = ll;
        float vv = row[NHID + NKVH * DHEAD + h * DHEAD + d];
        bsplit(vv, hh, ll);
        size_t vidx = (((size_t)b * NKVH + h) * DHEAD + d) * NS + s;
        g_vth[vidx] = hh;
        g_vtl[vidx] = ll;
    }
}

// ------------------------- tensor-core flash attention ---------------------
// BM=64, BN=64, 4 warps. bf16 hi/lo 3-pass for QK^T and PV. fp32 softmax.
// Pipelined: K(t+1) loads overlap softmax+PV; V(t+1) overlaps next QK^T.
// Q fragments hoisted to registers (loop-invariant).
#define AQ_HI 0
#define AQ_LO (64 * 272)
#define AK_HI (2 * 64 * 272)
#define AK_LO (3 * 64 * 272)
#define AVT_HI (4 * 64 * 272)
#define AVT_LO (4 * 64 * 272 + 128 * 144)
#define ATTN_SMEM (4 * 64 * 272 + 2 * 128 * 144)  // 106496

__global__ void __launch_bounds__(128) flash_attn_tc() {
    extern __shared__ char smem[];
    const uint32_t sb = smem_u32(smem);
    const int tid = threadIdx.x;
    const int lane = tid & 31;
    const int w = tid >> 5;
    const int qb = gridDim.x - 1 - blockIdx.x;
    const int h = blockIdx.y;
    const int b = blockIdx.z;
    const int hk = h >> 2;
    const int q0 = qb * 64;
    const int wrow = w * 16;

    const __nv_bfloat16* Qh = g_qh + ((size_t)(b * NHEADS + h) * NS + q0) * DHEAD;
    const __nv_bfloat16* Ql = g_ql + ((size_t)(b * NHEADS + h) * NS + q0) * DHEAD;
    const __nv_bfloat16* Kh = g_kh + ((size_t)(b * NKVH + hk) * NS) * DHEAD;
    const __nv_bfloat16* Kl = g_kl + ((size_t)(b * NKVH + hk) * NS) * DHEAD;
    const __nv_bfloat16* Vth = g_vth + ((size_t)(b * NKVH + hk) * DHEAD) * NS;
    const __nv_bfloat16* Vtl = g_vtl + ((size_t)(b * NKVH + hk) * DHEAD) * NS;

    auto load_K = [&](int t) {
#pragma unroll
        for (int i = 0; i < 8; i++) {
            int q = tid + i * 128;
            int r = q >> 4, cc = q & 15;
            cp16(sb + AK_HI + r * 272 + cc * 16, Kh + (size_t)(t * 64 + r) * DHEAD + cc * 8);
            cp16(sb + AK_LO + r * 272 + cc * 16, Kl + (size_t)(t * 64 + r) * DHEAD + cc * 8);
        }
    };
    auto load_V = [&](int t) {
#pragma unroll
        for (int i = 0; i < 8; i++) {
            int q = tid + i * 128;
            int d = q >> 3, cc = q & 7;
            cp16(sb + AVT_HI + d * 144 + cc * 16, Vth + (size_t)d * NS + t * 64 + cc * 8);
            cp16(sb + AVT_LO + d * 144 + cc * 16, Vtl + (size_t)d * NS + t * 64 + cc * 8);
        }
    };

    // issue Q (group), K0 (group), V0 (group)
#pragma unroll
    for (int i = 0; i < 8; i++) {
        int q = tid + i * 128;
        int r = q >> 4, cc = q & 15;
        cp16(sb + AQ_HI + r * 272 + cc * 16, Qh + (size_t)r * DHEAD + cc * 8);
        cp16(sb + AQ_LO + r * 272 + cc * 16, Ql + (size_t)r * DHEAD + cc * 8);
    }
    CP_COMMIT();
    load_K(0);
    CP_COMMIT();
    load_V(0);
    CP_COMMIT();

    const int lr = (lane & 7) + ((lane >> 3) & 1) * 8;
    const int lc16 = (lane >> 4) * 16;

    // wait for Q (2 groups may remain pending), hoist Q fragments to regs
    CP_WAIT2();
    __syncthreads();
    uint32_t qfh[8][4], qfl[8][4];
#pragma unroll
    for (int kc = 0; kc < 8; kc++) {
        const uint32_t qaddr = sb + AQ_HI + (wrow + lr) * 272 + kc * 32 + lc16;
        ldsm4(qfh[kc], qaddr);
        ldsm4(qfl[kc], qaddr + (AQ_LO - AQ_HI));
    }

    float of[16][4];
#pragma unroll
    for (int f = 0; f < 16; f++)
#pragma unroll
        for (int e = 0; e < 4; e++) of[f][e] = 0.0f;
    float m0 = -1e30f, m1 = -1e30f, l0 = 0.0f, l1 = 0.0f;

    for (int t = 0; t <= qb; t++) {
        CP_WAIT1();  // K(t) complete (V(t) may still be in flight)
        __syncthreads();

        // S = Q K^T : 16 rows x 64 cols per warp
        float sc[8][4];
#pragma unroll
        for (int nf = 0; nf < 8; nf++)
#pragma unroll
            for (int e = 0; e < 4; e++) sc[nf][e] = 0.0f;

#pragma unroll
        for (int kc = 0; kc < 8; kc++) {
#pragma unroll
            for (int np = 0; np < 4; np++) {
                uint32_t kh4[4], kl4[4];
                const uint32_t kaddr = sb + AK_HI + (np * 16 + lr) * 272 + kc * 32 + lc16;
                ldsm4(kh4, kaddr);
                ldsm4(kl4, kaddr + (AK_LO - AK_HI));
                uint32_t bh0[2] = {kh4[0], kh4[2]}, bh1[2] = {kh4[1], kh4[3]};
                uint32_t bl0[2] = {kl4[0], kl4[2]}, bl1[2] = {kl4[1], kl4[3]};
                mma16816(sc[2 * np], qfh[kc], bh0);
                mma16816(sc[2 * np], qfh[kc], bl0);
                mma16816(sc[2 * np], qfl[kc], bh0);
                mma16816(sc[2 * np + 1], qfh[kc], bh1);
                mma16816(sc[2 * np + 1], qfh[kc], bl1);
                mma16816(sc[2 * np + 1], qfl[kc], bh1);
            }
        }

        __syncthreads();  // all warps done reading K smem
        if (t < qb) {     // prefetch K(t+1) — overlaps softmax + PV below
            load_K(t + 1);
            CP_COMMIT();
        }

        if (t == qb) {  // causal mask on diagonal tile
            const int row0 = q0 + wrow + (lane >> 2);
            const int colb = t * 64 + 2 * (lane & 3);
#pragma unroll
            for (int nf = 0; nf < 8; nf++) {
                const int cb = colb + 8 * nf;
                if (cb > row0) sc[nf][0] = -1e30f;
                if (cb + 1 > row0) sc[nf][1] = -1e30f;
                if (cb > row0 + 8) sc[nf][2] = -1e30f;
                if (cb + 1 > row0 + 8) sc[nf][3] = -1e30f;
            }
        }

        // online softmax (rows r=lane/4 and r+8)
        float rmax0 = -1e30f, rmax1 = -1e30f;
#pragma unroll
        for (int nf = 0; nf < 8; nf++) {
            rmax0 = fmaxf(rmax0, fmaxf(sc[nf][0], sc[nf][1]));
            rmax1 = fmaxf(rmax1, fmaxf(sc[nf][2], sc[nf][3]));
        }
        rmax0 = fmaxf(rmax0, __shfl_xor_sync(0xffffffffu, rmax0, 1));
        rmax0 = fmaxf(rmax0, __shfl_xor_sync(0xffffffffu, rmax0, 2));
        rmax1 = fmaxf(rmax1, __shfl_xor_sync(0xffffffffu, rmax1, 1));
        rmax1 = fmaxf(rmax1, __shfl_xor_sync(0xffffffffu, rmax1, 2));
        const float mn0 = fmaxf(m0, rmax0);
        const float mn1 = fmaxf(m1, rmax1);
        const float scl0 = __expf(m0 - mn0);
        const float scl1 = __expf(m1 - mn1);
        float rs0 = 0.0f, rs1 = 0.0f;
#pragma unroll
        for (int nf = 0; nf < 8; nf++) {
            sc[nf][0] = __expf(sc[nf][0] - mn0); rs0 += sc[nf][0];
            sc[nf][1] = __expf(sc[nf][1] - mn0); rs0 += sc[nf][1];
            sc[nf][2] = __expf(sc[nf][2] - mn1); rs1 += sc[nf][2];
            sc[nf][3] = __expf(sc[nf][3] - mn1); rs1 += sc[nf][3];
        }
        rs0 += __shfl_xor_sync(0xffffffffu, rs0, 1);
        rs0 += __shfl_xor_sync(0xffffffffu, rs0, 2);
        rs1 += __shfl_xor_sync(0xffffffffu, rs1, 1);
        rs1 += __shfl_xor_sync(0xffffffffu, rs1, 2);
        l0 = l0 * scl0 + rs0;
        l1 = l1 * scl1 + rs1;
        m0 = mn0;
        m1 = mn1;
#pragma unroll
        for (int f = 0; f < 16; f++) {
            of[f][0] *= scl0; of[f][1] *= scl0;
            of[f][2] *= scl1; of[f][3] *= scl1;
        }

        // wait for V(t)
        if (t < qb) CP_WAIT1(); else CP_WAIT0();
        __syncthreads();

        // O += P V  (P frags reuse S accumulator layout)
#pragma unroll
        for (int kb = 0; kb < 4; kb++) {
            uint32_t ph[4], pl[4];
            split_pack2(sc[2 * kb][0], sc[2 * kb][1], ph[0], pl[0]);
            split_pack2(sc[2 * kb][2], sc[2 * kb][3], ph[1], pl[1]);
            split_pack2(sc[2 * kb + 1][0], sc[2 * kb + 1][1], ph[2], pl[2]);
            split_pack2(sc[2 * kb + 1][2], sc[2 * kb + 1][3], ph[3], pl[3]);
#pragma unroll
            for (int np = 0; np < 8; np++) {
                uint32_t vh4[4], vl4[4];
                const uint32_t vaddr = sb + AVT_HI + (np * 16 + lr) * 144 + kb * 32 + lc16;
                ldsm4(vh4, vaddr);
                ldsm4(vl4, vaddr + (AVT_LO - AVT_HI));
                uint32_t bh0[2] = {vh4[0], vh4[2]}, bh1[2] = {vh4[1], vh4[3]};
                uint32_t bl0[2] = {vl4[0], vl4[2]}, bl1[2] = {vl4[1], vl4[3]};
                mma16816(of[2 * np], ph, bh0);
                mma16816(of[2 * np], ph, bl0);
                mma16816(of[2 * np], pl, bh0);
                mma16816(of[2 * np + 1], ph, bh1);
                mma16816(of[2 * np + 1], ph, bl1);
                mma16816(of[2 * np + 1], pl, bh1);
            }
        }

        __syncthreads();  // all warps done reading V smem
        if (t < qb) {     // prefetch V(t+1) — overlaps next tile's QK^T
            load_V(t + 1);
            CP_COMMIT();
        }
    }

    // epilogue: O /= l, split to bf16 hi/lo, write head-major
    const float inv0 = 1.0f / l0;
    const float inv1 = 1.0f / l1;
    const int r0g = q0 + wrow + (lane >> 2);
    const int colb = 2 * (lane & 3);
#pragma unroll
    for (int nf = 0; nf < 16; nf++) {
        const int col = h * DHEAD + 8 * nf + colb;
        float x0 = of[nf][0] * inv0, y0 = of[nf][1] * inv0;
        float x1 = of[nf][2] * inv1, y1 = of[nf][3] * inv1;
        __nv_bfloat16 xh, xl, yh, yl;
        bsplit(x0, xh, xl); bsplit(y0, yh, yl);
        size_t i0 = (size_t)(b * NS + r0g) * NHID + col;
        *(__nv_bfloat162*)(g_at_hi + i0) = {xh, yh};
        *(__nv_bfloat162*)(g_at_lo + i0) = {xl, yl};
        bsplit(x1, xh, xl); bsplit(y1, yh, yl);
        size_t i1 = (size_t)(b * NS + r0g + 8) * NHID + col;
        *(__nv_bfloat162*)(g_at_hi + i1) = {xh, yh};
        *(__nv_bfloat162*)(g_at_lo + i1) = {xl, yl};
    }
}

// ------------------------- launch ------------------------------------------
extern "C" void kernel_launch(void* const* d_in, const int* in_sizes, int n_in,
                              void* d_out, int out_size) {
    const float* hidden = (const float*)d_in[0];
    const void* pos = d_in[1];
    const float* Wqkv = (const float*)d_in[2];
    const float* Wout = (const float*)d_in[3];
    float* out = (float*)d_out;

    void *p_qkv, *p_hh, *p_hl, *p_w1h, *p_w1l, *p_w2h, *p_w2l, *p_ah, *p_al;
    cudaGetSymbolAddress(&p_qkv, g_qkv);
    cudaGetSymbolAddress(&p_hh, g_hid_hi);
    cudaGetSymbolAddress(&p_hl, g_hid_lo);
    cudaGetSymbolAddress(&p_w1h, g_w1_hi);
    cudaGetSymbolAddress(&p_w1l, g_w1_lo);
    cudaGetSymbolAddress(&p_w2h, g_w2_hi);
    cudaGetSymbolAddress(&p_w2l, g_w2_lo);
    cudaGetSymbolAddress(&p_ah, g_at_hi);
    cudaGetSymbolAddress(&p_al, g_at_lo);

    const int nHid = NB * NS * NHID;
    const int nW1 = NQKV * NHID;
    const int nW2 = NHID * NHID;

    split_bf16<<<(nHid / 4 + 255) / 256, 256>>>(hidden, (__nv_bfloat16*)p_hh,
                                                (__nv_bfloat16*)p_hl, nHid / 4);
    split_bf16<<<(nW1 / 4 + 255) / 256, 256>>>(Wqkv, (__nv_bfloat16*)p_w1h,
                                               (__nv_bfloat16*)p_w1l, nW1 / 4);
    split_bf16<<<(nW2 / 4 + 255) / 256, 256>>>(Wout, (__nv_bfloat16*)p_w2h,
                                               (__nv_bfloat16*)p_w2l, nW2 / 4);

    // 1) QKV projection + clamp
    {
        cudaFuncSetAttribute(gemm_hmma<1>, cudaFuncAttributeMaxDynamicSharedMemorySize, GSMEM);
        dim3 grid(NQKV / 128, (NB * NS) / 128);
        gemm_hmma<1><<<grid, 256, GSMEM>>>(
            (const __nv_bfloat16*)p_hh, (const __nv_bfloat16*)p_hl,
            (const __nv_bfloat16*)p_w1h, (const __nv_bfloat16*)p_w1l,
            (float*)p_qkv, NB * NS, NQKV, NHID);
    }
    // 2) RoPE + scatter (emits bf16 hi/lo Q, K, V^T)
    rope_scatter<<<NB * NS, 128>>>(pos);

    // 3) tensor-core causal flash attention (pipelined)
    {
        cudaFuncSetAttribute(flash_attn_tc, cudaFuncAttributeMaxDynamicSharedMemorySize, ATTN_SMEM);
        dim3 grid(NS / 64, NHEADS, NB);
        flash_attn_tc<<<grid, 128, ATTN_SMEM>>>();
    }
    // 4) output projection
    {
        cudaFuncSetAttribute(gemm_hmma<0>, cudaFuncAttributeMaxDynamicSharedMemorySize, GSMEM);
        dim3 grid(NHID / 128, (NB * NS) / 128);
        gemm_hmma<0><<<grid, 256, GSMEM>>>(
            (const __nv_bfloat16*)p_ah, (const __nv_bfloat16*)p_al,
            (const __nv_bfloat16*)p_w2h, (const __nv_bfloat16*)p_w2l,
            out, NB * NS, NHID, NHID);
    }
}

// round 7
// speedup vs baseline: 2.7651x; 1.0329x over previous
#include <cuda_runtime.h>
#include <cuda_bf16.h>
#include <cstdint>
#include <math.h>

#define NB 2
#define NS 2048
#define NHID 2048
#define NHEADS 16
#define NKVH 4
#define DHEAD 128
#define NQKV 3072

// ------------------------- scratch (static device globals; no allocs) ------
static __device__ float g_qkv[(size_t)NB * NS * NQKV];

static __device__ __nv_bfloat16 g_qh[(size_t)NB * NHEADS * NS * DHEAD];
static __device__ __nv_bfloat16 g_ql[(size_t)NB * NHEADS * NS * DHEAD];
static __device__ __nv_bfloat16 g_kh[(size_t)NB * NKVH * NS * DHEAD];
static __device__ __nv_bfloat16 g_kl[(size_t)NB * NKVH * NS * DHEAD];
static __device__ __nv_bfloat16 g_vth[(size_t)NB * NKVH * DHEAD * NS];  // [b,hk,d,s]
static __device__ __nv_bfloat16 g_vtl[(size_t)NB * NKVH * DHEAD * NS];

static __device__ __nv_bfloat16 g_hid_hi[(size_t)NB * NS * NHID];
static __device__ __nv_bfloat16 g_hid_lo[(size_t)NB * NS * NHID];
static __device__ __nv_bfloat16 g_w1_hi[(size_t)NQKV * NHID];
static __device__ __nv_bfloat16 g_w1_lo[(size_t)NQKV * NHID];
static __device__ __nv_bfloat16 g_w2_hi[(size_t)NHID * NHID];
static __device__ __nv_bfloat16 g_w2_lo[(size_t)NHID * NHID];
static __device__ __nv_bfloat16 g_at_hi[(size_t)NB * NS * NHID];
static __device__ __nv_bfloat16 g_at_lo[(size_t)NB * NS * NHID];

// ------------------------- PTX helpers (baseline ISA only) -----------------
__device__ __forceinline__ uint32_t smem_u32(const void* p) {
    uint32_t a;
    asm("{ .reg .u64 t; cvta.to.shared.u64 t, %1; cvt.u32.u64 %0, t; }"
        : "=r"(a) : "l"(p));
    return a;
}

__device__ __forceinline__ void cp16(uint32_t dst, const void* src) {
    asm volatile("cp.async.cg.shared.global [%0], [%1], 16;"
                 :: "r"(dst), "l"(src));
}
#define CP_COMMIT() asm volatile("cp.async.commit_group;" ::: "memory")
#define CP_WAIT0() asm volatile("cp.async.wait_group 0;" ::: "memory")
#define CP_WAIT1() asm volatile("cp.async.wait_group 1;" ::: "memory")
#define CP_WAIT2() asm volatile("cp.async.wait_group 2;" ::: "memory")

__device__ __forceinline__ void ldsm4(uint32_t* r, uint32_t addr) {
    asm volatile("ldmatrix.sync.aligned.m8n8.x4.shared.b16 {%0,%1,%2,%3}, [%4];"
                 : "=r"(r[0]), "=r"(r[1]), "=r"(r[2]), "=r"(r[3]) : "r"(addr));
}

__device__ __forceinline__ void mma16816(float* c, const uint32_t* a, const uint32_t* b) {
    asm volatile(
        "mma.sync.aligned.m16n8k16.row.col.f32.bf16.bf16.f32 "
        "{%0,%1,%2,%3}, {%4,%5,%6,%7}, {%8,%9}, {%0,%1,%2,%3};"
        : "+f"(c[0]), "+f"(c[1]), "+f"(c[2]), "+f"(c[3])
        : "r"(a[0]), "r"(a[1]), "r"(a[2]), "r"(a[3]), "r"(b[0]), "r"(b[1]));
}

__device__ __forceinline__ void bsplit(float x, __nv_bfloat16& h, __nv_bfloat16& l) {
    h = __float2bfloat16(x);
    l = __float2bfloat16(x - __bfloat162float(h));
}

__device__ __forceinline__ void split_pack2(float a, float b, uint32_t& hi, uint32_t& lo) {
    __nv_bfloat16 ah, al, bh, bl;
    bsplit(a, ah, al);
    bsplit(b, bh, bl);
    hi = (uint32_t)__bfloat16_as_ushort(ah) | ((uint32_t)__bfloat16_as_ushort(bh) << 16);
    lo = (uint32_t)__bfloat16_as_ushort(al) | ((uint32_t)__bfloat16_as_ushort(bl) << 16);
}

// ------------------------- split fp32 -> bf16 hi/lo ------------------------
__global__ void __launch_bounds__(256) split_bf16(const float* __restrict__ x,
                                                  __nv_bfloat16* __restrict__ hi,
                                                  __nv_bfloat16* __restrict__ lo,
                                                  int n4) {
    int i = blockIdx.x * 256 + threadIdx.x;
    if (i >= n4) return;
    float4 v = ((const float4*)x)[i];
    __nv_bfloat16 h0, l0, h1, l1, h2, l2, h3, l3;
    bsplit(v.x, h0, l0); bsplit(v.y, h1, l1);
    bsplit(v.z, h2, l2); bsplit(v.w, h3, l3);
    __nv_bfloat162 hh0 = {h0, h1}, hh1 = {h2, h3};
    __nv_bfloat162 ll0 = {l0, l1}, ll1 = {l2, l3};
    ((__nv_bfloat162*)hi)[2 * i] = hh0;
    ((__nv_bfloat162*)hi)[2 * i + 1] = hh1;
    ((__nv_bfloat162*)lo)[2 * i] = ll0;
    ((__nv_bfloat162*)lo)[2 * i + 1] = ll1;
}

// ------------------------- HMMA GEMM: C[M,N] = A[M,K] * B[N,K]^T -----------
// Pass-major MMA ordering (16 independent accs between dependent MMAs);
// single __syncthreads per K-iteration.
#define ROWB 80
#define OPSZ (128 * ROWB)
#define STAGESZ (4 * OPSZ)
#define GSMEM (2 * STAGESZ)

template <int CLAMP>
__global__ void __launch_bounds__(256) gemm_hmma(const __nv_bfloat16* __restrict__ Ahi,
                                                 const __nv_bfloat16* __restrict__ Alo,
                                                 const __nv_bfloat16* __restrict__ Bhi,
                                                 const __nv_bfloat16* __restrict__ Blo,
                                                 float* __restrict__ C,
                                                 int M, int N, int K) {
    extern __shared__ char smem[];
    const uint32_t sb = smem_u32(smem);
    const int tid = threadIdx.x;
    const int lane = tid & 31;
    const int wid = tid >> 5;
    const int wm = (wid & 1) * 64;
    const int wn = (wid >> 1) * 32;
    const int bx = blockIdx.x;
    const int by = blockIdx.y;

    const int r0 = tid >> 2, c0 = (tid & 3);
    const int r1 = (tid + 256) >> 2, c1 = tid & 3;

    const __nv_bfloat16* gA[2] = {Ahi, Alo};
    const __nv_bfloat16* gB[2] = {Bhi, Blo};

    auto load_stage = [&](int stage, int kt) {
        const uint32_t s = sb + stage * STAGESZ;
        const int kc = kt * 32;
#pragma unroll
        for (int hl = 0; hl < 2; hl++) {
            const __nv_bfloat16* A = gA[hl] + (size_t)(by * 128) * K + kc;
            const __nv_bfloat16* B = gB[hl] + (size_t)(bx * 128) * K + kc;
            const uint32_t sA = s + hl * OPSZ;
            const uint32_t sB = s + (2 + hl) * OPSZ;
            cp16(sA + r0 * ROWB + c0 * 16, A + (size_t)r0 * K + c0 * 8);
            cp16(sA + r1 * ROWB + c1 * 16, A + (size_t)r1 * K + c1 * 8);
            cp16(sB + r0 * ROWB + c0 * 16, B + (size_t)r0 * K + c0 * 8);
            cp16(sB + r1 * ROWB + c1 * 16, B + (size_t)r1 * K + c1 * 8);
        }
    };

    float acc[4][4][4];
#pragma unroll
    for (int i = 0; i < 4; i++)
#pragma unroll
        for (int j = 0; j < 4; j++)
#pragma unroll
            for (int e = 0; e < 4; e++) acc[i][j][e] = 0.0f;

    const int KT = K >> 5;
    load_stage(0, 0);
    CP_COMMIT();

    const int lrow = (lane & 7) + ((lane >> 3) & 1) * 8;
    const int lchunk = lane >> 4;

    for (int kt = 0; kt < KT; kt++) {
        CP_WAIT0();
        __syncthreads();
        if (kt + 1 < KT) {  // overlaps the compute below
            load_stage((kt + 1) & 1, kt + 1);
            CP_COMMIT();
        }

        const uint32_t s = sb + (kt & 1) * STAGESZ;
#pragma unroll
        for (int ks = 0; ks < 2; ks++) {
            const int cb = 2 * ks;
            uint32_t ah[4][4], al[4][4], bh[4][2], bl[4][2];
#pragma unroll
            for (int mf = 0; mf < 4; mf++) {
                const uint32_t ra = (wm + mf * 16 + lrow) * ROWB + (cb + lchunk) * 16;
                ldsm4(ah[mf], s + ra);
                ldsm4(al[mf], s + OPSZ + ra);
            }
#pragma unroll
            for (int nf2 = 0; nf2 < 2; nf2++) {
                const uint32_t rb = (wn + nf2 * 16 + lrow) * ROWB + (cb + lchunk) * 16;
                uint32_t th[4], tl[4];
                ldsm4(th, s + 2 * OPSZ + rb);
                ldsm4(tl, s + 3 * OPSZ + rb);
                bh[nf2 * 2][0] = th[0]; bh[nf2 * 2 + 1][0] = th[1];
                bh[nf2 * 2][1] = th[2]; bh[nf2 * 2 + 1][1] = th[3];
                bl[nf2 * 2][0] = tl[0]; bl[nf2 * 2 + 1][0] = tl[1];
                bl[nf2 * 2][1] = tl[2]; bl[nf2 * 2 + 1][1] = tl[3];
            }
            // pass-major: 16 independent MMAs per pass
#pragma unroll
            for (int mf = 0; mf < 4; mf++)
#pragma unroll
                for (int nf = 0; nf < 4; nf++)
                    mma16816(acc[mf][nf], ah[mf], bh[nf]);
#pragma unroll
            for (int mf = 0; mf < 4; mf++)
#pragma unroll
                for (int nf = 0; nf < 4; nf++)
                    mma16816(acc[mf][nf], ah[mf], bl[nf]);
#pragma unroll
            for (int mf = 0; mf < 4; mf++)
#pragma unroll
                for (int nf = 0; nf < 4; nf++)
                    mma16816(acc[mf][nf], al[mf], bh[nf]);
        }
    }

    const int erow = lane >> 2;
    const int ecol = (lane & 3) * 2;
#pragma unroll
    for (int mf = 0; mf < 4; mf++) {
#pragma unroll
        for (int nf = 0; nf < 4; nf++) {
            float* c = acc[mf][nf];
            if (CLAMP) {
#pragma unroll
                for (int e = 0; e < 4; e++)
                    c[e] = fminf(8.0f, fmaxf(-8.0f, c[e]));
            }
            const int row = by * 128 + wm + mf * 16 + erow;
            const int col = bx * 128 + wn + nf * 8 + ecol;
            float2 v0 = {c[0], c[1]};
            float2 v1 = {c[2], c[3]};
            *(float2*)(C + (size_t)row * N + col) = v0;
            *(float2*)(C + (size_t)(row + 8) * N + col) = v1;
        }
    }
}

// ------------------------- RoPE + scatter to bf16 hi/lo --------------------
__global__ void __launch_bounds__(128) rope_scatter(const void* __restrict__ pos_ids) {
    const int bs = blockIdx.x;
    const int b = bs / NS;
    const int s = bs % NS;
    const int d = threadIdx.x;
    const int dm = d & 63;

    const int* p32 = (const int*)pos_ids;
    const bool is64 = (p32[1] == 0) && (p32[3] == 0) && (p32[2 * NS + 1] == 0);
    const long long pv = is64 ? ((const long long*)pos_ids)[bs] : (long long)p32[bs];

    const double p = (double)pv;
    const double invf = pow(500000.0, -(double)dm / 64.0);
    double sd, cd;
    sincos(p * invf, &sd, &cd);
    const float c = (float)cd;
    const float sn = (float)sd;
    const float sign = (d < 64) ? -1.0f : 1.0f;
    const float qscale = 0.08838834764831845f;

    const float* row = g_qkv + (size_t)bs * NQKV;

#pragma unroll
    for (int h = 0; h < NHEADS; h++) {
        float v = row[h * DHEAD + d];
        float pr = row[h * DHEAD + (d ^ 64)];
        float qv = (v * c + sign * pr * sn) * qscale;
        __nv_bfloat16 hh, ll;
        bsplit(qv, hh, ll);
        size_t idx = (((size_t)b * NHEADS + h) * NS + s) * DHEAD + d;
        g_qh[idx] = hh;
        g_ql[idx] = ll;
    }
#pragma unroll
    for (int h = 0; h < NKVH; h++) {
        float v = row[NHID + h * DHEAD + d];
        float pr = row[NHID + h * DHEAD + (d ^ 64)];
        float kv = v * c + sign * pr * sn;
        __nv_bfloat16 hh, ll;
        bsplit(kv, hh, ll);
        size_t idx = (((size_t)b * NKVH + h) * NS + s) * DHEAD + d;
        g_kh[idx] = hh;
        g_kl[idx] = ll;
        float vv = row[NHID + NKVH * DHEAD + h * DHEAD + d];
        bsplit(vv, hh, ll);
        size_t vidx = (((size_t)b * NKVH + h) * DHEAD + d) * NS + s;
        g_vth[vidx] = hh;
        g_vtl[vidx] = ll;
    }
}

// ------------------------- tensor-core flash attention ---------------------
// BM=64, BN=64, 4 warps. bf16 hi/lo 3-pass, pass-major MMA ordering.
// Pipelined: K(t+1) loads overlap softmax+PV; V(t+1) overlaps next QK^T.
#define AQ_HI 0
#define AQ_LO (64 * 272)
#define AK_HI (2 * 64 * 272)
#define AK_LO (3 * 64 * 272)
#define AVT_HI (4 * 64 * 272)
#define AVT_LO (4 * 64 * 272 + 128 * 144)
#define ATTN_SMEM (4 * 64 * 272 + 2 * 128 * 144)  // 106496

__global__ void __launch_bounds__(128) flash_attn_tc() {
    extern __shared__ char smem[];
    const uint32_t sb = smem_u32(smem);
    const int tid = threadIdx.x;
    const int lane = tid & 31;
    const int w = tid >> 5;
    const int qb = gridDim.x - 1 - blockIdx.x;
    const int h = blockIdx.y;
    const int b = blockIdx.z;
    const int hk = h >> 2;
    const int q0 = qb * 64;
    const int wrow = w * 16;

    const __nv_bfloat16* Qh = g_qh + ((size_t)(b * NHEADS + h) * NS + q0) * DHEAD;
    const __nv_bfloat16* Ql = g_ql + ((size_t)(b * NHEADS + h) * NS + q0) * DHEAD;
    const __nv_bfloat16* Kh = g_kh + ((size_t)(b * NKVH + hk) * NS) * DHEAD;
    const __nv_bfloat16* Kl = g_kl + ((size_t)(b * NKVH + hk) * NS) * DHEAD;
    const __nv_bfloat16* Vth = g_vth + ((size_t)(b * NKVH + hk) * DHEAD) * NS;
    const __nv_bfloat16* Vtl = g_vtl + ((size_t)(b * NKVH + hk) * DHEAD) * NS;

    auto load_K = [&](int t) {
#pragma unroll
        for (int i = 0; i < 8; i++) {
            int q = tid + i * 128;
            int r = q >> 4, cc = q & 15;
            cp16(sb + AK_HI + r * 272 + cc * 16, Kh + (size_t)(t * 64 + r) * DHEAD + cc * 8);
            cp16(sb + AK_LO + r * 272 + cc * 16, Kl + (size_t)(t * 64 + r) * DHEAD + cc * 8);
        }
    };
    auto load_V = [&](int t) {
#pragma unroll
        for (int i = 0; i < 8; i++) {
            int q = tid + i * 128;
            int d = q >> 3, cc = q & 7;
            cp16(sb + AVT_HI + d * 144 + cc * 16, Vth + (size_t)d * NS + t * 64 + cc * 8);
            cp16(sb + AVT_LO + d * 144 + cc * 16, Vtl + (size_t)d * NS + t * 64 + cc * 8);
        }
    };

    // issue Q (group), K0 (group), V0 (group)
#pragma unroll
    for (int i = 0; i < 8; i++) {
        int q = tid + i * 128;
        int r = q >> 4, cc = q & 15;
        cp16(sb + AQ_HI + r * 272 + cc * 16, Qh + (size_t)r * DHEAD + cc * 8);
        cp16(sb + AQ_LO + r * 272 + cc * 16, Ql + (size_t)r * DHEAD + cc * 8);
    }
    CP_COMMIT();
    load_K(0);
    CP_COMMIT();
    load_V(0);
    CP_COMMIT();

    const int lr = (lane & 7) + ((lane >> 3) & 1) * 8;
    const int lc16 = (lane >> 4) * 16;

    CP_WAIT2();
    __syncthreads();
    uint32_t qfh[8][4], qfl[8][4];
#pragma unroll
    for (int kc = 0; kc < 8; kc++) {
        const uint32_t qaddr = sb + AQ_HI + (wrow + lr) * 272 + kc * 32 + lc16;
        ldsm4(qfh[kc], qaddr);
        ldsm4(qfl[kc], qaddr + (AQ_LO - AQ_HI));
    }

    float of[16][4];
#pragma unroll
    for (int f = 0; f < 16; f++)
#pragma unroll
        for (int e = 0; e < 4; e++) of[f][e] = 0.0f;
    float m0 = -1e30f, m1 = -1e30f, l0 = 0.0f, l1 = 0.0f;

    for (int t = 0; t <= qb; t++) {
        CP_WAIT1();  // K(t) complete (V(t) may still be in flight)
        __syncthreads();

        // S = Q K^T : 16 rows x 64 cols per warp, pass-major
        float sc[8][4];
#pragma unroll
        for (int nf = 0; nf < 8; nf++)
#pragma unroll
            for (int e = 0; e < 4; e++) sc[nf][e] = 0.0f;

#pragma unroll
        for (int kc = 0; kc < 8; kc++) {
            uint32_t bh0[4][2], bh1[4][2], bl0[4][2], bl1[4][2];
#pragma unroll
            for (int np = 0; np < 4; np++) {
                uint32_t kh4[4], kl4[4];
                const uint32_t kaddr = sb + AK_HI + (np * 16 + lr) * 272 + kc * 32 + lc16;
                ldsm4(kh4, kaddr);
                ldsm4(kl4, kaddr + (AK_LO - AK_HI));
                bh0[np][0] = kh4[0]; bh0[np][1] = kh4[2];
                bh1[np][0] = kh4[1]; bh1[np][1] = kh4[3];
                bl0[np][0] = kl4[0]; bl0[np][1] = kl4[2];
                bl1[np][0] = kl4[1]; bl1[np][1] = kl4[3];
            }
#pragma unroll
            for (int np = 0; np < 4; np++) {
                mma16816(sc[2 * np], qfh[kc], bh0[np]);
                mma16816(sc[2 * np + 1], qfh[kc], bh1[np]);
            }
#pragma unroll
            for (int np = 0; np < 4; np++) {
                mma16816(sc[2 * np], qfh[kc], bl0[np]);
                mma16816(sc[2 * np + 1], qfh[kc], bl1[np]);
            }
#pragma unroll
            for (int np = 0; np < 4; np++) {
                mma16816(sc[2 * np], qfl[kc], bh0[np]);
                mma16816(sc[2 * np + 1], qfl[kc], bh1[np]);
            }
        }

        __syncthreads();  // all warps done reading K smem
        if (t < qb) {     // prefetch K(t+1) — overlaps softmax + PV below
            load_K(t + 1);
            CP_COMMIT();
        }

        if (t == qb) {  // causal mask on diagonal tile
            const int row0 = q0 + wrow + (lane >> 2);
            const int colb = t * 64 + 2 * (lane & 3);
#pragma unroll
            for (int nf = 0; nf < 8; nf++) {
                const int cb = colb + 8 * nf;
                if (cb > row0) sc[nf][0] = -1e30f;
                if (cb + 1 > row0) sc[nf][1] = -1e30f;
                if (cb > row0 + 8) sc[nf][2] = -1e30f;
                if (cb + 1 > row0 + 8) sc[nf][3] = -1e30f;
            }
        }

        // online softmax (rows r=lane/4 and r+8)
        float rmax0 = -1e30f, rmax1 = -1e30f;
#pragma unroll
        for (int nf = 0; nf < 8; nf++) {
            rmax0 = fmaxf(rmax0, fmaxf(sc[nf][0], sc[nf][1]));
            rmax1 = fmaxf(rmax1, fmaxf(sc[nf][2], sc[nf][3]));
        }
        rmax0 = fmaxf(rmax0, __shfl_xor_sync(0xffffffffu, rmax0, 1));
        rmax0 = fmaxf(rmax0, __shfl_xor_sync(0xffffffffu, rmax0, 2));
        rmax1 = fmaxf(rmax1, __shfl_xor_sync(0xffffffffu, rmax1, 1));
        rmax1 = fmaxf(rmax1, __shfl_xor_sync(0xffffffffu, rmax1, 2));
        const float mn0 = fmaxf(m0, rmax0);
        const float mn1 = fmaxf(m1, rmax1);
        const float scl0 = __expf(m0 - mn0);
        const float scl1 = __expf(m1 - mn1);
        float rs0 = 0.0f, rs1 = 0.0f;
#pragma unroll
        for (int nf = 0; nf < 8; nf++) {
            sc[nf][0] = __expf(sc[nf][0] - mn0); rs0 += sc[nf][0];
            sc[nf][1] = __expf(sc[nf][1] - mn0); rs0 += sc[nf][1];
            sc[nf][2] = __expf(sc[nf][2] - mn1); rs1 += sc[nf][2];
            sc[nf][3] = __expf(sc[nf][3] - mn1); rs1 += sc[nf][3];
        }
        rs0 += __shfl_xor_sync(0xffffffffu, rs0, 1);
        rs0 += __shfl_xor_sync(0xffffffffu, rs0, 2);
        rs1 += __shfl_xor_sync(0xffffffffu, rs1, 1);
        rs1 += __shfl_xor_sync(0xffffffffu, rs1, 2);
        l0 = l0 * scl0 + rs0;
        l1 = l1 * scl1 + rs1;
        m0 = mn0;
        m1 = mn1;
#pragma unroll
        for (int f = 0; f < 16; f++) {
            of[f][0] *= scl0; of[f][1] *= scl0;
            of[f][2] *= scl1; of[f][3] *= scl1;
        }

        // wait for V(t)
        if (t < qb) CP_WAIT1(); else CP_WAIT0();
        __syncthreads();

        // O += P V  — np pairs, pass-major (distance 4)
#pragma unroll
        for (int kb = 0; kb < 4; kb++) {
            uint32_t ph[4], pl[4];
            split_pack2(sc[2 * kb][0], sc[2 * kb][1], ph[0], pl[0]);
            split_pack2(sc[2 * kb][2], sc[2 * kb][3], ph[1], pl[1]);
            split_pack2(sc[2 * kb + 1][0], sc[2 * kb + 1][1], ph[2], pl[2]);
            split_pack2(sc[2 * kb + 1][2], sc[2 * kb + 1][3], ph[3], pl[3]);
#pragma unroll
            for (int npp = 0; npp < 4; npp++) {
                const int np0 = 2 * npp, np1 = 2 * npp + 1;
                uint32_t vhA[4], vlA[4], vhB[4], vlB[4];
                const uint32_t vaddrA = sb + AVT_HI + (np0 * 16 + lr) * 144 + kb * 32 + lc16;
                const uint32_t vaddrB = sb + AVT_HI + (np1 * 16 + lr) * 144 + kb * 32 + lc16;
                ldsm4(vhA, vaddrA);
                ldsm4(vlA, vaddrA + (AVT_LO - AVT_HI));
                ldsm4(vhB, vaddrB);
                ldsm4(vlB, vaddrB + (AVT_LO - AVT_HI));
                uint32_t h0A[2] = {vhA[0], vhA[2]}, h1A[2] = {vhA[1], vhA[3]};
                uint32_t l0A[2] = {vlA[0], vlA[2]}, l1A[2] = {vlA[1], vlA[3]};
                uint32_t h0B[2] = {vhB[0], vhB[2]}, h1B[2] = {vhB[1], vhB[3]};
                uint32_t l0B[2] = {vlB[0], vlB[2]}, l1B[2] = {vlB[1], vlB[3]};
                mma16816(of[2 * np0], ph, h0A);
                mma16816(of[2 * np0 + 1], ph, h1A);
                mma16816(of[2 * np1], ph, h0B);
                mma16816(of[2 * np1 + 1], ph, h1B);
                mma16816(of[2 * np0], ph, l0A);
                mma16816(of[2 * np0 + 1], ph, l1A);
                mma16816(of[2 * np1], ph, l0B);
                mma16816(of[2 * np1 + 1], ph, l1B);
                mma16816(of[2 * np0], pl, h0A);
                mma16816(of[2 * np0 + 1], pl, h1A);
                mma16816(of[2 * np1], pl, h0B);
                mma16816(of[2 * np1 + 1], pl, h1B);
            }
        }

        __syncthreads();  // all warps done reading V smem
        if (t < qb) {     // prefetch V(t+1) — overlaps next tile's QK^T
            load_V(t + 1);
            CP_COMMIT();
        }
    }

    // epilogue: O /= l, split to bf16 hi/lo, write head-major
    const float inv0 = 1.0f / l0;
    const float inv1 = 1.0f / l1;
    const int r0g = q0 + wrow + (lane >> 2);
    const int colb = 2 * (lane & 3);
#pragma unroll
    for (int nf = 0; nf < 16; nf++) {
        const int col = h * DHEAD + 8 * nf + colb;
        float x0 = of[nf][0] * inv0, y0 = of[nf][1] * inv0;
        float x1 = of[nf][2] * inv1, y1 = of[nf][3] * inv1;
        __nv_bfloat16 xh, xl, yh, yl;
        bsplit(x0, xh, xl); bsplit(y0, yh, yl);
        size_t i0 = (size_t)(b * NS + r0g) * NHID + col;
        *(__nv_bfloat162*)(g_at_hi + i0) = {xh, yh};
        *(__nv_bfloat162*)(g_at_lo + i0) = {xl, yl};
        bsplit(x1, xh, xl); bsplit(y1, yh, yl);
        size_t i1 = (size_t)(b * NS + r0g + 8) * NHID + col;
        *(__nv_bfloat162*)(g_at_hi + i1) = {xh, yh};
        *(__nv_bfloat162*)(g_at_lo + i1) = {xl, yl};
    }
}

// ------------------------- launch ------------------------------------------
extern "C" void kernel_launch(void* const* d_in, const int* in_sizes, int n_in,
                              void* d_out, int out_size) {
    const float* hidden = (const float*)d_in[0];
    const void* pos = d_in[1];
    const float* Wqkv = (const float*)d_in[2];
    const float* Wout = (const float*)d_in[3];
    float* out = (float*)d_out;

    void *p_qkv, *p_hh, *p_hl, *p_w1h, *p_w1l, *p_w2h, *p_w2l, *p_ah, *p_al;
    cudaGetSymbolAddress(&p_qkv, g_qkv);
    cudaGetSymbolAddress(&p_hh, g_hid_hi);
    cudaGetSymbolAddress(&p_hl, g_hid_lo);
    cudaGetSymbolAddress(&p_w1h, g_w1_hi);
    cudaGetSymbolAddress(&p_w1l, g_w1_lo);
    cudaGetSymbolAddress(&p_w2h, g_w2_hi);
    cudaGetSymbolAddress(&p_w2l, g_w2_lo);
    cudaGetSymbolAddress(&p_ah, g_at_hi);
    cudaGetSymbolAddress(&p_al, g_at_lo);

    const int nHid = NB * NS * NHID;
    const int nW1 = NQKV * NHID;
    const int nW2 = NHID * NHID;

    split_bf16<<<(nHid / 4 + 255) / 256, 256>>>(hidden, (__nv_bfloat16*)p_hh,
                                                (__nv_bfloat16*)p_hl, nHid / 4);
    split_bf16<<<(nW1 / 4 + 255) / 256, 256>>>(Wqkv, (__nv_bfloat16*)p_w1h,
                                               (__nv_bfloat16*)p_w1l, nW1 / 4);
    split_bf16<<<(nW2 / 4 + 255) / 256, 256>>>(Wout, (__nv_bfloat16*)p_w2h,
                                               (__nv_bfloat16*)p_w2l, nW2 / 4);

    // 1) QKV projection + clamp
    {
        cudaFuncSetAttribute(gemm_hmma<1>, cudaFuncAttributeMaxDynamicSharedMemorySize, GSMEM);
        dim3 grid(NQKV / 128, (NB * NS) / 128);
        gemm_hmma<1><<<grid, 256, GSMEM>>>(
            (const __nv_bfloat16*)p_hh, (const __nv_bfloat16*)p_hl,
            (const __nv_bfloat16*)p_w1h, (const __nv_bfloat16*)p_w1l,
            (float*)p_qkv, NB * NS, NQKV, NHID);
    }
    // 2) RoPE + scatter (emits bf16 hi/lo Q, K, V^T)
    rope_scatter<<<NB * NS, 128>>>(pos);

    // 3) tensor-core causal flash attention (pipelined, pass-major)
    {
        cudaFuncSetAttribute(flash_attn_tc, cudaFuncAttributeMaxDynamicSharedMemorySize, ATTN_SMEM);
        dim3 grid(NS / 64, NHEADS, NB);
        flash_attn_tc<<<grid, 128, ATTN_SMEM>>>();
    }
    // 4) output projection
    {
        cudaFuncSetAttribute(gemm_hmma<0>, cudaFuncAttributeMaxDynamicSharedMemorySize, GSMEM);
        dim3 grid(NHID / 128, (NB * NS) / 128);
        gemm_hmma<0><<<grid, 256, GSMEM>>>(
            (const __nv_bfloat16*)p_ah, (const __nv_bfloat16*)p_al,
            (const __nv_bfloat16*)p_w2h, (const __nv_bfloat16*)p_w2l,
            out, NB * NS, NHID, NHID);
    }
}

// round 8
// speedup vs baseline: 3.2744x; 1.1842x over previous
#include <cuda_runtime.h>
#include <cuda_bf16.h>
#include <cstdint>
#include <math.h>

#define NB 2
#define NS 2048
#define NHID 2048
#define NHEADS 16
#define NKVH 4
#define DHEAD 128
#define NQKV 3072

// ------------------------- scratch (static device globals; no allocs) ------
static __device__ float g_qkv[(size_t)NB * NS * NQKV];

static __device__ __nv_bfloat16 g_qh[(size_t)NB * NHEADS * NS * DHEAD];
static __device__ __nv_bfloat16 g_ql[(size_t)NB * NHEADS * NS * DHEAD];
static __device__ __nv_bfloat16 g_kh[(size_t)NB * NKVH * NS * DHEAD];
static __device__ __nv_bfloat16 g_kl[(size_t)NB * NKVH * NS * DHEAD];
static __device__ __nv_bfloat16 g_vh[(size_t)NB * NKVH * NS * DHEAD];  // row-major like K
static __device__ __nv_bfloat16 g_vl[(size_t)NB * NKVH * NS * DHEAD];

static __device__ __nv_bfloat16 g_hid_hi[(size_t)NB * NS * NHID];
static __device__ __nv_bfloat16 g_hid_lo[(size_t)NB * NS * NHID];
static __device__ __nv_bfloat16 g_w1_hi[(size_t)NQKV * NHID];
static __device__ __nv_bfloat16 g_w1_lo[(size_t)NQKV * NHID];
static __device__ __nv_bfloat16 g_w2_hi[(size_t)NHID * NHID];
static __device__ __nv_bfloat16 g_w2_lo[(size_t)NHID * NHID];
static __device__ __nv_bfloat16 g_at_hi[(size_t)NB * NS * NHID];
static __device__ __nv_bfloat16 g_at_lo[(size_t)NB * NS * NHID];

// ------------------------- PTX helpers (baseline ISA only) -----------------
__device__ __forceinline__ uint32_t smem_u32(const void* p) {
    uint32_t a;
    asm("{ .reg .u64 t; cvta.to.shared.u64 t, %1; cvt.u32.u64 %0, t; }"
        : "=r"(a) : "l"(p));
    return a;
}

__device__ __forceinline__ void cp16(uint32_t dst, const void* src) {
    asm volatile("cp.async.cg.shared.global [%0], [%1], 16;"
                 :: "r"(dst), "l"(src));
}
#define CP_COMMIT() asm volatile("cp.async.commit_group;" ::: "memory")
#define CP_WAIT0() asm volatile("cp.async.wait_group 0;" ::: "memory")
#define CP_WAIT1() asm volatile("cp.async.wait_group 1;" ::: "memory")
#define CP_WAIT2() asm volatile("cp.async.wait_group 2;" ::: "memory")

__device__ __forceinline__ void ldsm4(uint32_t* r, uint32_t addr) {
    asm volatile("ldmatrix.sync.aligned.m8n8.x4.shared.b16 {%0,%1,%2,%3}, [%4];"
                 : "=r"(r[0]), "=r"(r[1]), "=r"(r[2]), "=r"(r[3]) : "r"(addr));
}

__device__ __forceinline__ void ldsm4t(uint32_t* r, uint32_t addr) {
    asm volatile("ldmatrix.sync.aligned.m8n8.x4.trans.shared.b16 {%0,%1,%2,%3}, [%4];"
                 : "=r"(r[0]), "=r"(r[1]), "=r"(r[2]), "=r"(r[3]) : "r"(addr));
}

__device__ __forceinline__ void mma16816(float* c, const uint32_t* a, const uint32_t* b) {
    asm volatile(
        "mma.sync.aligned.m16n8k16.row.col.f32.bf16.bf16.f32 "
        "{%0,%1,%2,%3}, {%4,%5,%6,%7}, {%8,%9}, {%0,%1,%2,%3};"
        : "+f"(c[0]), "+f"(c[1]), "+f"(c[2]), "+f"(c[3])
        : "r"(a[0]), "r"(a[1]), "r"(a[2]), "r"(a[3]), "r"(b[0]), "r"(b[1]));
}

__device__ __forceinline__ void bsplit(float x, __nv_bfloat16& h, __nv_bfloat16& l) {
    h = __float2bfloat16(x);
    l = __float2bfloat16(x - __bfloat162float(h));
}

__device__ __forceinline__ void split_pack2(float a, float b, uint32_t& hi, uint32_t& lo) {
    __nv_bfloat16 ah, al, bh, bl;
    bsplit(a, ah, al);
    bsplit(b, bh, bl);
    hi = (uint32_t)__bfloat16_as_ushort(ah) | ((uint32_t)__bfloat16_as_ushort(bh) << 16);
    lo = (uint32_t)__bfloat16_as_ushort(al) | ((uint32_t)__bfloat16_as_ushort(bl) << 16);
}

#define SWZ128(x) ((x) ^ (((x) >> 3) & 0x70))

// ------------------------- split fp32 -> bf16 hi/lo ------------------------
__global__ void __launch_bounds__(256) split_bf16(const float* __restrict__ x,
                                                  __nv_bfloat16* __restrict__ hi,
                                                  __nv_bfloat16* __restrict__ lo,
                                                  int n4) {
    int i = blockIdx.x * 256 + threadIdx.x;
    if (i >= n4) return;
    float4 v = ((const float4*)x)[i];
    __nv_bfloat16 h0, l0, h1, l1, h2, l2, h3, l3;
    bsplit(v.x, h0, l0); bsplit(v.y, h1, l1);
    bsplit(v.z, h2, l2); bsplit(v.w, h3, l3);
    __nv_bfloat162 hh0 = {h0, h1}, hh1 = {h2, h3};
    __nv_bfloat162 ll0 = {l0, l1}, ll1 = {l2, l3};
    ((__nv_bfloat162*)hi)[2 * i] = hh0;
    ((__nv_bfloat162*)hi)[2 * i + 1] = hh1;
    ((__nv_bfloat162*)lo)[2 * i] = ll0;
    ((__nv_bfloat162*)lo)[2 * i + 1] = ll1;
}

// ------------------------- HMMA GEMM: C[M,N] = A[M,K] * B[N,K]^T -----------
// 128x64 CTA tile, 32x32 warp tile, BK=32. hi/lo merged into single SW128
// 128B rows (chunks 0-3 = hi, 4-7 = lo). 48KB smem, 3 CTAs/SM.
#define GST 24576          // stage: A 16KB + B 8KB
#define GSMEM (2 * GST)    // 49152

template <int CLAMP>
__global__ void __launch_bounds__(256, 3) gemm_hmma(const __nv_bfloat16* __restrict__ Ahi,
                                                    const __nv_bfloat16* __restrict__ Alo,
                                                    const __nv_bfloat16* __restrict__ Bhi,
                                                    const __nv_bfloat16* __restrict__ Blo,
                                                    float* __restrict__ C,
                                                    int M, int N, int K) {
    extern __shared__ char smem[];
    const uint32_t sb = smem_u32(smem);
    const int tid = threadIdx.x;
    const int lane = tid & 31;
    const int wid = tid >> 5;
    const int wm = (wid & 3) * 32;   // M offset within 128
    const int wn = (wid >> 2) * 32;  // N offset within 64
    const int bx = blockIdx.x;
    const int by = blockIdx.y;

    auto load_stage = [&](int st, int kt) {
        const uint32_t s = sb + st * GST;
        const int kc = kt * 32;
#pragma unroll
        for (int i = 0; i < 4; i++) {
            const int q = tid + i * 256;
            const int r = q >> 3, c = q & 7;
            const __nv_bfloat16* srcA =
                (c < 4 ? Ahi : Alo) + (size_t)(by * 128 + r) * K + kc + (c & 3) * 8;
            cp16(s + SWZ128(r * 128 + c * 16), srcA);
        }
#pragma unroll
        for (int i = 0; i < 2; i++) {
            const int q = tid + i * 256;
            const int r = q >> 3, c = q & 7;
            const __nv_bfloat16* srcB =
                (c < 4 ? Bhi : Blo) + (size_t)(bx * 64 + r) * K + kc + (c & 3) * 8;
            cp16(s + 16384 + SWZ128(r * 128 + c * 16), srcB);
        }
    };

    float acc[2][4][4];
#pragma unroll
    for (int i = 0; i < 2; i++)
#pragma unroll
        for (int j = 0; j < 4; j++)
#pragma unroll
            for (int e = 0; e < 4; e++) acc[i][j][e] = 0.0f;

    const int KT = K >> 5;
    load_stage(0, 0);
    CP_COMMIT();

    const int lr = (lane & 7) + ((lane >> 3) & 1) * 8;
    const int lc = lane >> 4;  // 0/1

    for (int kt = 0; kt < KT; kt++) {
        CP_WAIT0();
        __syncthreads();
        if (kt + 1 < KT) {
            load_stage((kt + 1) & 1, kt + 1);
            CP_COMMIT();
        }

        const uint32_t s = sb + (kt & 1) * GST;
#pragma unroll
        for (int ks = 0; ks < 2; ks++) {
            const int ch = 2 * ks + lc;  // hi chunk 0..3, lo at +4
            uint32_t bh[4][2], bl[4][2];
#pragma unroll
            for (int nf2 = 0; nf2 < 2; nf2++) {
                const uint32_t rb = (wn + nf2 * 16 + lr) * 128;
                uint32_t th[4], tl[4];
                ldsm4(th, s + 16384 + SWZ128(rb + ch * 16));
                ldsm4(tl, s + 16384 + SWZ128(rb + (ch + 4) * 16));
                bh[nf2 * 2][0] = th[0]; bh[nf2 * 2 + 1][0] = th[1];
                bh[nf2 * 2][1] = th[2]; bh[nf2 * 2 + 1][1] = th[3];
                bl[nf2 * 2][0] = tl[0]; bl[nf2 * 2 + 1][0] = tl[1];
                bl[nf2 * 2][1] = tl[2]; bl[nf2 * 2 + 1][1] = tl[3];
            }
#pragma unroll
            for (int mf = 0; mf < 2; mf++) {
                uint32_t ah[4], al[4];
                const uint32_t ra = (wm + mf * 16 + lr) * 128;
                ldsm4(ah, s + SWZ128(ra + ch * 16));
                ldsm4(al, s + SWZ128(ra + (ch + 4) * 16));
#pragma unroll
                for (int nf = 0; nf < 4; nf++) mma16816(acc[mf][nf], ah, bh[nf]);
#pragma unroll
                for (int nf = 0; nf < 4; nf++) mma16816(acc[mf][nf], ah, bl[nf]);
#pragma unroll
                for (int nf = 0; nf < 4; nf++) mma16816(acc[mf][nf], al, bh[nf]);
            }
        }
    }

    const int erow = lane >> 2;
    const int ecol = (lane & 3) * 2;
#pragma unroll
    for (int mf = 0; mf < 2; mf++) {
#pragma unroll
        for (int nf = 0; nf < 4; nf++) {
            float* c = acc[mf][nf];
            if (CLAMP) {
#pragma unroll
                for (int e = 0; e < 4; e++)
                    c[e] = fminf(8.0f, fmaxf(-8.0f, c[e]));
            }
            const int row = by * 128 + wm + mf * 16 + erow;
            const int col = bx * 64 + wn + nf * 8 + ecol;
            float2 v0 = {c[0], c[1]};
            float2 v1 = {c[2], c[3]};
            *(float2*)(C + (size_t)row * N + col) = v0;
            *(float2*)(C + (size_t)(row + 8) * N + col) = v1;
        }
    }
}

// ------------------------- RoPE + scatter to bf16 hi/lo --------------------
__global__ void __launch_bounds__(128) rope_scatter(const void* __restrict__ pos_ids) {
    const int bs = blockIdx.x;
    const int b = bs / NS;
    const int s = bs % NS;
    const int d = threadIdx.x;
    const int dm = d & 63;

    const int* p32 = (const int*)pos_ids;
    const bool is64 = (p32[1] == 0) && (p32[3] == 0) && (p32[2 * NS + 1] == 0);
    const long long pv = is64 ? ((const long long*)pos_ids)[bs] : (long long)p32[bs];

    const double p = (double)pv;
    const double C_LN = 0.20503692777194264;  // ln(500000)/64
    const double invf = exp(-(double)dm * C_LN);
    double sd, cd;
    sincos(p * invf, &sd, &cd);
    const float c = (float)cd;
    const float sn = (float)sd;
    const float sign = (d < 64) ? -1.0f : 1.0f;
    const float qscale = 0.08838834764831845f;

    const float* row = g_qkv + (size_t)bs * NQKV;

#pragma unroll
    for (int h = 0; h < NHEADS; h++) {
        float v = row[h * DHEAD + d];
        float pr = row[h * DHEAD + (d ^ 64)];
        float qv = (v * c + sign * pr * sn) * qscale;
        __nv_bfloat16 hh, ll;
        bsplit(qv, hh, ll);
        size_t idx = (((size_t)b * NHEADS + h) * NS + s) * DHEAD + d;
        g_qh[idx] = hh;
        g_ql[idx] = ll;
    }
#pragma unroll
    for (int h = 0; h < NKVH; h++) {
        float v = row[NHID + h * DHEAD + d];
        float pr = row[NHID + h * DHEAD + (d ^ 64)];
        float kv = v * c + sign * pr * sn;
        __nv_bfloat16 hh, ll;
        bsplit(kv, hh, ll);
        size_t idx = (((size_t)b * NKVH + h) * NS + s) * DHEAD + d;
        g_kh[idx] = hh;
        g_kl[idx] = ll;
        float vv = row[NHID + NKVH * DHEAD + h * DHEAD + d];
        bsplit(vv, hh, ll);
        g_vh[idx] = hh;   // row-major (coalesced) — attention transposes via ldsm.trans
        g_vl[idx] = ll;
    }
}

// ------------------------- tensor-core flash attention ---------------------
// BM=64, BN=64, 4 warps. bf16 hi/lo 3-pass. V row-major; PV B-frags via
// ldmatrix.trans. Pipelined K/V prefetch.
#define AQ_HI 0
#define AQ_LO 17408
#define AK_HI 34816
#define AK_LO 52224
#define AV_HI 69632
#define AV_LO 87040
#define ATTN_SMEM 104448

__global__ void __launch_bounds__(128) flash_attn_tc() {
    extern __shared__ char smem[];
    const uint32_t sb = smem_u32(smem);
    const int tid = threadIdx.x;
    const int lane = tid & 31;
    const int w = tid >> 5;
    const int qb = gridDim.x - 1 - blockIdx.x;
    const int h = blockIdx.y;
    const int b = blockIdx.z;
    const int hk = h >> 2;
    const int q0 = qb * 64;
    const int wrow = w * 16;

    const __nv_bfloat16* Qh = g_qh + ((size_t)(b * NHEADS + h) * NS + q0) * DHEAD;
    const __nv_bfloat16* Ql = g_ql + ((size_t)(b * NHEADS + h) * NS + q0) * DHEAD;
    const __nv_bfloat16* Kh = g_kh + ((size_t)(b * NKVH + hk) * NS) * DHEAD;
    const __nv_bfloat16* Kl = g_kl + ((size_t)(b * NKVH + hk) * NS) * DHEAD;
    const __nv_bfloat16* Vh = g_vh + ((size_t)(b * NKVH + hk) * NS) * DHEAD;
    const __nv_bfloat16* Vl = g_vl + ((size_t)(b * NKVH + hk) * NS) * DHEAD;

    auto load_K = [&](int t) {
#pragma unroll
        for (int i = 0; i < 8; i++) {
            int q = tid + i * 128;
            int r = q >> 4, cc = q & 15;
            cp16(sb + AK_HI + r * 272 + cc * 16, Kh + (size_t)(t * 64 + r) * DHEAD + cc * 8);
            cp16(sb + AK_LO + r * 272 + cc * 16, Kl + (size_t)(t * 64 + r) * DHEAD + cc * 8);
        }
    };
    auto load_V = [&](int t) {
#pragma unroll
        for (int i = 0; i < 8; i++) {
            int q = tid + i * 128;
            int r = q >> 4, cc = q & 15;
            cp16(sb + AV_HI + r * 272 + cc * 16, Vh + (size_t)(t * 64 + r) * DHEAD + cc * 8);
            cp16(sb + AV_LO + r * 272 + cc * 16, Vl + (size_t)(t * 64 + r) * DHEAD + cc * 8);
        }
    };

#pragma unroll
    for (int i = 0; i < 8; i++) {
        int q = tid + i * 128;
        int r = q >> 4, cc = q & 15;
        cp16(sb + AQ_HI + r * 272 + cc * 16, Qh + (size_t)r * DHEAD + cc * 8);
        cp16(sb + AQ_LO + r * 272 + cc * 16, Ql + (size_t)r * DHEAD + cc * 8);
    }
    CP_COMMIT();
    load_K(0);
    CP_COMMIT();
    load_V(0);
    CP_COMMIT();

    const int lr = (lane & 7) + ((lane >> 3) & 1) * 8;
    const int lc16 = (lane >> 4) * 16;

    CP_WAIT2();
    __syncthreads();
    uint32_t qfh[8][4], qfl[8][4];
#pragma unroll
    for (int kc = 0; kc < 8; kc++) {
        const uint32_t qaddr = sb + AQ_HI + (wrow + lr) * 272 + kc * 32 + lc16;
        ldsm4(qfh[kc], qaddr);
        ldsm4(qfl[kc], qaddr + (AQ_LO - AQ_HI));
    }

    float of[16][4];
#pragma unroll
    for (int f = 0; f < 16; f++)
#pragma unroll
        for (int e = 0; e < 4; e++) of[f][e] = 0.0f;
    float m0 = -1e30f, m1 = -1e30f, l0 = 0.0f, l1 = 0.0f;

    for (int t = 0; t <= qb; t++) {
        CP_WAIT1();  // K(t) complete
        __syncthreads();

        float sc[8][4];
#pragma unroll
        for (int nf = 0; nf < 8; nf++)
#pragma unroll
            for (int e = 0; e < 4; e++) sc[nf][e] = 0.0f;

#pragma unroll
        for (int kc = 0; kc < 8; kc++) {
            uint32_t bh0[4][2], bh1[4][2], bl0[4][2], bl1[4][2];
#pragma unroll
            for (int np = 0; np < 4; np++) {
                uint32_t kh4[4], kl4[4];
                const uint32_t kaddr = sb + AK_HI + (np * 16 + lr) * 272 + kc * 32 + lc16;
                ldsm4(kh4, kaddr);
                ldsm4(kl4, kaddr + (AK_LO - AK_HI));
                bh0[np][0] = kh4[0]; bh0[np][1] = kh4[2];
                bh1[np][0] = kh4[1]; bh1[np][1] = kh4[3];
                bl0[np][0] = kl4[0]; bl0[np][1] = kl4[2];
                bl1[np][0] = kl4[1]; bl1[np][1] = kl4[3];
            }
#pragma unroll
            for (int np = 0; np < 4; np++) {
                mma16816(sc[2 * np], qfh[kc], bh0[np]);
                mma16816(sc[2 * np + 1], qfh[kc], bh1[np]);
            }
#pragma unroll
            for (int np = 0; np < 4; np++) {
                mma16816(sc[2 * np], qfh[kc], bl0[np]);
                mma16816(sc[2 * np + 1], qfh[kc], bl1[np]);
            }
#pragma unroll
            for (int np = 0; np < 4; np++) {
                mma16816(sc[2 * np], qfl[kc], bh0[np]);
                mma16816(sc[2 * np + 1], qfl[kc], bh1[np]);
            }
        }

        __syncthreads();
        if (t < qb) {
            load_K(t + 1);
            CP_COMMIT();
        }

        if (t == qb) {
            const int row0 = q0 + wrow + (lane >> 2);
            const int colb = t * 64 + 2 * (lane & 3);
#pragma unroll
            for (int nf = 0; nf < 8; nf++) {
                const int cb = colb + 8 * nf;
                if (cb > row0) sc[nf][0] = -1e30f;
                if (cb + 1 > row0) sc[nf][1] = -1e30f;
                if (cb > row0 + 8) sc[nf][2] = -1e30f;
                if (cb + 1 > row0 + 8) sc[nf][3] = -1e30f;
            }
        }

        float rmax0 = -1e30f, rmax1 = -1e30f;
#pragma unroll
        for (int nf = 0; nf < 8; nf++) {
            rmax0 = fmaxf(rmax0, fmaxf(sc[nf][0], sc[nf][1]));
            rmax1 = fmaxf(rmax1, fmaxf(sc[nf][2], sc[nf][3]));
        }
        rmax0 = fmaxf(rmax0, __shfl_xor_sync(0xffffffffu, rmax0, 1));
        rmax0 = fmaxf(rmax0, __shfl_xor_sync(0xffffffffu, rmax0, 2));
        rmax1 = fmaxf(rmax1, __shfl_xor_sync(0xffffffffu, rmax1, 1));
        rmax1 = fmaxf(rmax1, __shfl_xor_sync(0xffffffffu, rmax1, 2));
        const float mn0 = fmaxf(m0, rmax0);
        const float mn1 = fmaxf(m1, rmax1);
        const float scl0 = __expf(m0 - mn0);
        const float scl1 = __expf(m1 - mn1);
        float rs0 = 0.0f, rs1 = 0.0f;
#pragma unroll
        for (int nf = 0; nf < 8; nf++) {
            sc[nf][0] = __expf(sc[nf][0] - mn0); rs0 += sc[nf][0];
            sc[nf][1] = __expf(sc[nf][1] - mn0); rs0 += sc[nf][1];
            sc[nf][2] = __expf(sc[nf][2] - mn1); rs1 += sc[nf][2];
            sc[nf][3] = __expf(sc[nf][3] - mn1); rs1 += sc[nf][3];
        }
        rs0 += __shfl_xor_sync(0xffffffffu, rs0, 1);
        rs0 += __shfl_xor_sync(0xffffffffu, rs0, 2);
        rs1 += __shfl_xor_sync(0xffffffffu, rs1, 1);
        rs1 += __shfl_xor_sync(0xffffffffu, rs1, 2);
        l0 = l0 * scl0 + rs0;
        l1 = l1 * scl1 + rs1;
        m0 = mn0;
        m1 = mn1;
#pragma unroll
        for (int f = 0; f < 16; f++) {
            of[f][0] *= scl0; of[f][1] *= scl0;
            of[f][2] *= scl1; of[f][3] *= scl1;
        }

        if (t < qb) CP_WAIT1(); else CP_WAIT0();
        __syncthreads();

        // O += P V : B frags from row-major V via ldsm.trans
        // trans frags: {r0,r1} = d-block np*16..+7, {r2,r3} = +8..15
#pragma unroll
        for (int kb = 0; kb < 4; kb++) {
            uint32_t ph[4], pl[4];
            split_pack2(sc[2 * kb][0], sc[2 * kb][1], ph[0], pl[0]);
            split_pack2(sc[2 * kb][2], sc[2 * kb][3], ph[1], pl[1]);
            split_pack2(sc[2 * kb + 1][0], sc[2 * kb + 1][1], ph[2], pl[2]);
            split_pack2(sc[2 * kb + 1][2], sc[2 * kb + 1][3], ph[3], pl[3]);
            const uint32_t vbase = sb + AV_HI + (kb * 16 + lr) * 272 + lc16;
#pragma unroll
            for (int npp = 0; npp < 4; npp++) {
                const int np0 = 2 * npp, np1 = 2 * npp + 1;
                uint32_t vhA[4], vlA[4], vhB[4], vlB[4];
                ldsm4t(vhA, vbase + np0 * 32);
                ldsm4t(vlA, vbase + np0 * 32 + (AV_LO - AV_HI));
                ldsm4t(vhB, vbase + np1 * 32);
                ldsm4t(vlB, vbase + np1 * 32 + (AV_LO - AV_HI));
                uint32_t h0A[2] = {vhA[0], vhA[1]}, h1A[2] = {vhA[2], vhA[3]};
                uint32_t l0A[2] = {vlA[0], vlA[1]}, l1A[2] = {vlA[2], vlA[3]};
                uint32_t h0B[2] = {vhB[0], vhB[1]}, h1B[2] = {vhB[2], vhB[3]};
                uint32_t l0B[2] = {vlB[0], vlB[1]}, l1B[2] = {vlB[2], vlB[3]};
                mma16816(of[2 * np0], ph, h0A);
                mma16816(of[2 * np0 + 1], ph, h1A);
                mma16816(of[2 * np1], ph, h0B);
                mma16816(of[2 * np1 + 1], ph, h1B);
                mma16816(of[2 * np0], ph, l0A);
                mma16816(of[2 * np0 + 1], ph, l1A);
                mma16816(of[2 * np1], ph, l0B);
                mma16816(of[2 * np1 + 1], ph, l1B);
                mma16816(of[2 * np0], pl, h0A);
                mma16816(of[2 * np0 + 1], pl, h1A);
                mma16816(of[2 * np1], pl, h0B);
                mma16816(of[2 * np1 + 1], pl, h1B);
            }
        }

        __syncthreads();
        if (t < qb) {
            load_V(t + 1);
            CP_COMMIT();
        }
    }

    const float inv0 = 1.0f / l0;
    const float inv1 = 1.0f / l1;
    const int r0g = q0 + wrow + (lane >> 2);
    const int colb = 2 * (lane & 3);
#pragma unroll
    for (int nf = 0; nf < 16; nf++) {
        const int col = h * DHEAD + 8 * nf + colb;
        float x0 = of[nf][0] * inv0, y0 = of[nf][1] * inv0;
        float x1 = of[nf][2] * inv1, y1 = of[nf][3] * inv1;
        __nv_bfloat16 xh, xl, yh, yl;
        bsplit(x0, xh, xl); bsplit(y0, yh, yl);
        size_t i0 = (size_t)(b * NS + r0g) * NHID + col;
        *(__nv_bfloat162*)(g_at_hi + i0) = {xh, yh};
        *(__nv_bfloat162*)(g_at_lo + i0) = {xl, yl};
        bsplit(x1, xh, xl); bsplit(y1, yh, yl);
        size_t i1 = (size_t)(b * NS + r0g + 8) * NHID + col;
        *(__nv_bfloat162*)(g_at_hi + i1) = {xh, yh};
        *(__nv_bfloat162*)(g_at_lo + i1) = {xl, yl};
    }
}

// ------------------------- launch ------------------------------------------
extern "C" void kernel_launch(void* const* d_in, const int* in_sizes, int n_in,
                              void* d_out, int out_size) {
    const float* hidden = (const float*)d_in[0];
    const void* pos = d_in[1];
    const float* Wqkv = (const float*)d_in[2];
    const float* Wout = (const float*)d_in[3];
    float* out = (float*)d_out;

    void *p_qkv, *p_hh, *p_hl, *p_w1h, *p_w1l, *p_w2h, *p_w2l, *p_ah, *p_al;
    cudaGetSymbolAddress(&p_qkv, g_qkv);
    cudaGetSymbolAddress(&p_hh, g_hid_hi);
    cudaGetSymbolAddress(&p_hl, g_hid_lo);
    cudaGetSymbolAddress(&p_w1h, g_w1_hi);
    cudaGetSymbolAddress(&p_w1l, g_w1_lo);
    cudaGetSymbolAddress(&p_w2h, g_w2_hi);
    cudaGetSymbolAddress(&p_w2l, g_w2_lo);
    cudaGetSymbolAddress(&p_ah, g_at_hi);
    cudaGetSymbolAddress(&p_al, g_at_lo);

    const int nHid = NB * NS * NHID;
    const int nW1 = NQKV * NHID;
    const int nW2 = NHID * NHID;

    split_bf16<<<(nHid / 4 + 255) / 256, 256>>>(hidden, (__nv_bfloat16*)p_hh,
                                                (__nv_bfloat16*)p_hl, nHid / 4);
    split_bf16<<<(nW1 / 4 + 255) / 256, 256>>>(Wqkv, (__nv_bfloat16*)p_w1h,
                                               (__nv_bfloat16*)p_w1l, nW1 / 4);
    split_bf16<<<(nW2 / 4 + 255) / 256, 256>>>(Wout, (__nv_bfloat16*)p_w2h,
                                               (__nv_bfloat16*)p_w2l, nW2 / 4);

    // 1) QKV projection + clamp
    {
        cudaFuncSetAttribute(gemm_hmma<1>, cudaFuncAttributeMaxDynamicSharedMemorySize, GSMEM);
        dim3 grid(NQKV / 64, (NB * NS) / 128);
        gemm_hmma<1><<<grid, 256, GSMEM>>>(
            (const __nv_bfloat16*)p_hh, (const __nv_bfloat16*)p_hl,
            (const __nv_bfloat16*)p_w1h, (const __nv_bfloat16*)p_w1l,
            (float*)p_qkv, NB * NS, NQKV, NHID);
    }
    // 2) RoPE + scatter (emits bf16 hi/lo Q, K, V; all coalesced)
    rope_scatter<<<NB * NS, 128>>>(pos);

    // 3) tensor-core causal flash attention
    {
        cudaFuncSetAttribute(flash_attn_tc, cudaFuncAttributeMaxDynamicSharedMemorySize, ATTN_SMEM);
        dim3 grid(NS / 64, NHEADS, NB);
        flash_attn_tc<<<grid, 128, ATTN_SMEM>>>();
    }
    // 4) output projection
    {
        cudaFuncSetAttribute(gemm_hmma<0>, cudaFuncAttributeMaxDynamicSharedMemorySize, GSMEM);
        dim3 grid(NHID / 64, (NB * NS) / 128);
        gemm_hmma<0><<<grid, 256, GSMEM>>>(
            (const __nv_bfloat16*)p_ah, (const __nv_bfloat16*)p_al,
            (const __nv_bfloat16*)p_w2h, (const __nv_bfloat16*)p_w2l,
            out, NB * NS, NHID, NHID);
    }
}